// round 5
// baseline (speedup 1.0000x reference)
#include <cuda_runtime.h>
#include <cuda_bf16.h>
#include <cstdint>

#define BATCH 64

// ------------------------- scratch (no allocs allowed) -------------------------
__device__ float    g_bufA[BATCH*32*160*160];   // conv1 out (fp32, for stats)
__device__ float    g_bufB[BATCH*32*160*160];   // rconv out (fp32, for pool)
__device__ uint32_t g_xHL[BATCH*3*170*170];     // input, packed hi/lo bf16
__device__ uint32_t g_actHL[BATCH*32*160*160];  // norm+PReLU(conv1 out), packed
__device__ uint32_t g_poolHL[BATCH*32*80*80];   // pooled, packed
__device__ float g_c4[BATCH*16*73*73];
__device__ float g_c5[BATCH*16*33*33];
__device__ float g_c6[BATCH*16*28*28];
__device__ float g_c7[BATCH*16*24*24];
__device__ float g_c8[BATCH*16*8*8];

__device__ uint32_t g_w1HL[32*384];    // conv1 w, K padded 363->384
__device__ uint32_t g_wrHL[32*320];    // rconv w, reordered k=t*32+ic, padded 288->320
__device__ uint32_t g_w4HL[16*2048];   // conv4 w

__device__ float g_wT5[1024*16];
__device__ float g_wT6[576*16];
__device__ float g_wT7[400*16];
__device__ float g_wT8[144*16];
__device__ float g_wTfc[1024*512];

__device__ float g_scale[512];   // [region(16)][channel(32)]
__device__ float g_shift[512];

// ------------------------- helpers -------------------------
__device__ __forceinline__ uint32_t smem_u32(const void* p) {
    uint32_t a;
    asm("{ .reg .u64 t; cvta.to.shared.u64 t, %1; cvt.u32.u64 %0, t; }" : "=r"(a) : "l"(p));
    return a;
}
__device__ __forceinline__ uint32_t sw128(uint32_t o) { return o ^ ((o >> 3) & 0x70); }

__device__ __forceinline__ uint32_t packHL(float v) {
    __nv_bfloat16 h = __float2bfloat16(v);
    float r = v - __bfloat162float(h);
    __nv_bfloat16 l = __float2bfloat16(r);
    uint16_t hb = *reinterpret_cast<uint16_t*>(&h);
    uint16_t lb = *reinterpret_cast<uint16_t*>(&l);
    return (uint32_t)hb | ((uint32_t)lb << 16);
}

__device__ __forceinline__ void ldsm4(uint32_t* r, uint32_t addr) {
    asm volatile("ldmatrix.sync.aligned.m8n8.x4.shared.b16 {%0,%1,%2,%3}, [%4];"
                 : "=r"(r[0]), "=r"(r[1]), "=r"(r[2]), "=r"(r[3]) : "r"(addr));
}

__device__ __forceinline__ void mma_bf16(float* c,
        uint32_t a0, uint32_t a1, uint32_t a2, uint32_t a3,
        uint32_t b0, uint32_t b1) {
    asm volatile(
        "mma.sync.aligned.m16n8k16.row.col.f32.bf16.bf16.f32 "
        "{%0,%1,%2,%3}, {%4,%5,%6,%7}, {%8,%9}, {%0,%1,%2,%3};"
        : "+f"(c[0]), "+f"(c[1]), "+f"(c[2]), "+f"(c[3])
        : "r"(a0), "r"(a1), "r"(a2), "r"(a3), "r"(b0), "r"(b1));
}

// tile byte offsets inside a buffer
#define OFF_AHI 0
#define OFF_ALO 16384
#define OFF_BHI 32768
#define OFF_BLO 36864
#define BUFSZ_N32 40960
#define C4_BHI 32768
#define C4_BLO 34816
#define BUFSZ_N16 36864

// consumer: 4 k-steps of one 64-wide K chunk, N=32 tiles
__device__ __forceinline__ void mma_chunk_n32(uint32_t sb, int wid, int lane, float* acc) {
#pragma unroll
    for (int ks = 0; ks < 4; ks++) {
        uint32_t a_hi[8], a_lo[8], b_hi[8], b_lo[8];
        uint32_t abyte = (uint32_t)((wid*32 + (lane & 15))*128 + (ks*16 + ((lane >> 4) << 3))*2);
        ldsm4(&a_hi[0], sb + OFF_AHI + sw128(abyte));
        ldsm4(&a_hi[4], sb + OFF_AHI + sw128(abyte) + 2048);
        ldsm4(&a_lo[0], sb + OFF_ALO + sw128(abyte));
        ldsm4(&a_lo[4], sb + OFF_ALO + sw128(abyte) + 2048);
        uint32_t bbyte = (uint32_t)(((((lane >> 4) << 3) + (lane & 7))*128) + (ks*16 + (lane & 8))*2);
        ldsm4(&b_hi[0], sb + OFF_BHI + sw128(bbyte));
        ldsm4(&b_hi[4], sb + OFF_BHI + sw128(bbyte) + 2048);
        ldsm4(&b_lo[0], sb + OFF_BLO + sw128(bbyte));
        ldsm4(&b_lo[4], sb + OFF_BLO + sw128(bbyte) + 2048);
#pragma unroll
        for (int mt = 0; mt < 2; mt++) {
#pragma unroll
            for (int nt = 0; nt < 4; nt++) {
                float* cc = acc + (mt*4 + nt)*4;
                const uint32_t* A  = a_hi + mt*4;
                const uint32_t* Al = a_lo + mt*4;
                uint32_t bh0 = b_hi[nt*2], bh1 = b_hi[nt*2+1];
                uint32_t bl0 = b_lo[nt*2], bl1 = b_lo[nt*2+1];
                mma_bf16(cc, A[0],A[1],A[2],A[3],   bh0, bh1);
                mma_bf16(cc, Al[0],Al[1],Al[2],Al[3], bh0, bh1);
                mma_bf16(cc, A[0],A[1],A[2],A[3],   bl0, bl1);
            }
        }
    }
}

// consumer: N=16 variant (conv4)
__device__ __forceinline__ void mma_chunk_n16(uint32_t sb, int wid, int lane, float* acc) {
#pragma unroll
    for (int ks = 0; ks < 4; ks++) {
        uint32_t a_hi[8], a_lo[8], b_hi[4], b_lo[4];
        uint32_t abyte = (uint32_t)((wid*32 + (lane & 15))*128 + (ks*16 + ((lane >> 4) << 3))*2);
        ldsm4(&a_hi[0], sb + OFF_AHI + sw128(abyte));
        ldsm4(&a_hi[4], sb + OFF_AHI + sw128(abyte) + 2048);
        ldsm4(&a_lo[0], sb + OFF_ALO + sw128(abyte));
        ldsm4(&a_lo[4], sb + OFF_ALO + sw128(abyte) + 2048);
        uint32_t bbyte = (uint32_t)(((((lane >> 4) << 3) + (lane & 7))*128) + (ks*16 + (lane & 8))*2);
        ldsm4(b_hi, sb + C4_BHI + sw128(bbyte));
        ldsm4(b_lo, sb + C4_BLO + sw128(bbyte));
#pragma unroll
        for (int mt = 0; mt < 2; mt++) {
#pragma unroll
            for (int nt = 0; nt < 2; nt++) {
                float* cc = acc + (mt*2 + nt)*4;
                const uint32_t* A  = a_hi + mt*4;
                const uint32_t* Al = a_lo + mt*4;
                uint32_t bh0 = b_hi[nt*2], bh1 = b_hi[nt*2+1];
                uint32_t bl0 = b_lo[nt*2], bl1 = b_lo[nt*2+1];
                mma_bf16(cc, A[0],A[1],A[2],A[3],   bh0, bh1);
                mma_bf16(cc, Al[0],Al[1],Al[2],Al[3], bh0, bh1);
                mma_bf16(cc, A[0],A[1],A[2],A[3],   bl0, bl1);
            }
        }
    }
}

// ------------------------- pre-pass kernels -------------------------
__global__ void split_x(const float* __restrict__ x) {
    int t = blockIdx.x * blockDim.x + threadIdx.x;
    if (t < BATCH*3*170*170) g_xHL[t] = packHL(x[t]);
}
__global__ void t_w1hl(const float* __restrict__ w) {
    int e = blockIdx.x * blockDim.x + threadIdx.x;
    if (e < 32*384) {
        int oc = e / 384, k = e - oc*384;
        g_w1HL[e] = (k < 363) ? packHL(w[oc*363 + k]) : 0u;
    }
}
__global__ void t_wrhl(const float* __restrict__ w) {
    int e = blockIdx.x * blockDim.x + threadIdx.x;
    if (e < 32*320) {
        int oc = e / 320, k = e - oc*320;
        int t9 = k >> 5, ic = k & 31;
        g_wrHL[e] = (t9 < 9) ? packHL(w[oc*288 + ic*9 + t9]) : 0u;
    }
}
__global__ void t_w4hl(const float* __restrict__ w) {
    int e = blockIdx.x * blockDim.x + threadIdx.x;
    if (e < 16*2048) g_w4HL[e] = packHL(w[e]);
}

// norm + PReLU + split, one pass
__global__ void act_kernel(const float* __restrict__ pa) {
    int t = blockIdx.x * blockDim.x + threadIdx.x;
    if (t >= BATCH*32*160*160) return;
    int xx = t % 160;
    int y  = (t / 160) % 160;
    int c  = (t / 25600) % 32;
    int region = (y / 40) * 4 + (xx / 40);
    float v = g_bufA[t];
    float r = fmaf(v, g_scale[region*32 + c], g_shift[region*32 + c]);
    float a = __ldg(pa);
    g_actHL[t] = packHL((r > 0.0f) ? r : a * r);
}

// ------------------------- producer fill functions -------------------------
__device__ __forceinline__ void c1_fill(char* buf, const uint32_t* __restrict__ xin,
                                        const int* soffs, int k0, int ptid) {
#pragma unroll 8
    for (int i = 0; i < 32; i++) {
        int2 o2 = *(const int2*)(soffs + k0 + 2*i);
        uint32_t v0 = (o2.x >= 0) ? __ldg(xin + o2.x) : 0u;
        uint32_t v1 = (o2.y >= 0) ? __ldg(xin + o2.y) : 0u;
        uint32_t off = sw128((uint32_t)(ptid * 128 + i * 4));
        *(uint32_t*)(buf + OFF_AHI + off) = __byte_perm(v0, v1, 0x5410);
        *(uint32_t*)(buf + OFF_ALO + off) = __byte_perm(v0, v1, 0x7632);
    }
#pragma unroll
    for (int e = ptid; e < 1024; e += 128) {
        int oc = e >> 5, i = e & 31;
        uint2 w2 = __ldg((const uint2*)(g_w1HL + oc*384 + k0 + 2*i));
        uint32_t off = sw128((uint32_t)(oc * 128 + i * 4));
        *(uint32_t*)(buf + OFF_BHI + off) = __byte_perm(w2.x, w2.y, 0x5410);
        *(uint32_t*)(buf + OFF_BLO + off) = __byte_perm(w2.x, w2.y, 0x7632);
    }
}

__device__ __forceinline__ void rc_fill(char* buf, const uint32_t* __restrict__ ain,
                                        int mask, int k0, int ptid) {
#pragma unroll 8
    for (int i = 0; i < 32; i++) {
        int k  = k0 + 2 * i;
        int t  = k >> 5;
        int ic = k & 31;          // even
        uint32_t v0 = 0u, v1 = 0u;
        if (t < 9 && ((mask >> t) & 1)) {
            int ty = t / 3;
            int dd = (ty - 1) * 160 + (t - ty * 3 - 1);
            const uint32_t* q = ain + ic * 25600 + dd;
            v0 = __ldg(q);
            v1 = __ldg(q + 25600);
        }
        uint32_t off = sw128((uint32_t)(ptid * 128 + i * 4));
        *(uint32_t*)(buf + OFF_AHI + off) = __byte_perm(v0, v1, 0x5410);
        *(uint32_t*)(buf + OFF_ALO + off) = __byte_perm(v0, v1, 0x7632);
    }
#pragma unroll
    for (int e = ptid; e < 1024; e += 128) {
        int oc = e >> 5, i = e & 31;
        uint2 w2 = __ldg((const uint2*)(g_wrHL + oc*320 + k0 + 2*i));
        uint32_t off = sw128((uint32_t)(oc * 128 + i * 4));
        *(uint32_t*)(buf + OFF_BHI + off) = __byte_perm(w2.x, w2.y, 0x5410);
        *(uint32_t*)(buf + OFF_BLO + off) = __byte_perm(w2.x, w2.y, 0x7632);
    }
}

__device__ __forceinline__ void c4_fill(char* buf, const uint32_t* __restrict__ pin,
                                        bool pv, int k0, int ptid) {
#pragma unroll 8
    for (int i = 0; i < 32; i++) {
        int k  = k0 + 2 * i;
        int ic = k >> 6;
        int r  = k & 63;
        int ky = r >> 3, kx = r & 7;   // kx even
        uint32_t v0 = 0u, v1 = 0u;
        if (pv) {
            const uint32_t* q = pin + ic * 6400 + ky * 80 + kx;
            v0 = __ldg(q);
            v1 = __ldg(q + 1);
        }
        uint32_t off = sw128((uint32_t)(ptid * 128 + i * 4));
        *(uint32_t*)(buf + OFF_AHI + off) = __byte_perm(v0, v1, 0x5410);
        *(uint32_t*)(buf + OFF_ALO + off) = __byte_perm(v0, v1, 0x7632);
    }
#pragma unroll
    for (int e = ptid; e < 512; e += 128) {
        int oc = e >> 5, i = e & 31;
        uint2 w2 = __ldg((const uint2*)(g_w4HL + oc*2048 + k0 + 2*i));
        uint32_t off = sw128((uint32_t)(oc * 128 + i * 4));
        *(uint32_t*)(buf + C4_BHI + off) = __byte_perm(w2.x, w2.y, 0x5410);
        *(uint32_t*)(buf + C4_BLO + off) = __byte_perm(w2.x, w2.y, 0x7632);
    }
}

// ------------------------- conv1: warp-specialized implicit GEMM, N=32, K=384 -------------------------
__global__ void __launch_bounds__(256) conv1_mma(const float* __restrict__ bias) {
    extern __shared__ char smem[];
    __shared__ int soffs[384];
    uint32_t sb = smem_u32(smem);
    int tid = threadIdx.x, wid = tid >> 5, lane = tid & 31;
    bool prod = tid >= 128;
    int ptid = tid & 127;

    for (int k = tid; k < 384; k += 256) {
        if (k < 363) {
            int ic = k / 121;
            int r  = k - ic * 121;
            int ky = r / 11, kx = r - ky * 11;
            soffs[k] = ic * 28900 + ky * 170 + kx;
        } else soffs[k] = -1;
    }

    int p  = blockIdx.x * 128 + ptid;
    int xo = p % 160, yo = (p / 160) % 160, b = p / 25600;
    const uint32_t* xin = g_xHL + b * 86700 + yo * 170 + xo;

    float acc[32];
#pragma unroll
    for (int i = 0; i < 32; i++) acc[i] = 0.f;
    __syncthreads();

    if (prod) c1_fill(smem, xin, soffs, 0, ptid);
    __syncthreads();
    for (int c = 0; c < 6; c++) {
        if (prod) { if (c + 1 < 6) c1_fill(smem + ((c+1)&1)*BUFSZ_N32, xin, soffs, (c+1)*64, ptid); }
        else      mma_chunk_n32(sb + (c&1)*BUFSZ_N32, wid, lane, acc);
        __syncthreads();
    }
    // epilogue
    float* stg = (float*)smem;
    if (!prod) {
#pragma unroll
        for (int mt = 0; mt < 2; mt++)
#pragma unroll
            for (int nt = 0; nt < 4; nt++)
#pragma unroll
                for (int r = 0; r < 4; r++) {
                    int row = wid*32 + mt*16 + (lane >> 2) + ((r >> 1) << 3);
                    int col = nt*8 + ((lane & 3) << 1) + (r & 1);
                    stg[row*33 + col] = acc[(mt*4 + nt)*4 + r];
                }
    }
    __syncthreads();
    {
        float* op = g_bufA + (b * 32 * 160 + yo) * 160 + xo;
        int j0 = (tid >> 7) * 16;
#pragma unroll
        for (int j = 0; j < 16; j++) {
            int jj = j0 + j;
            op[jj * 25600] = stg[ptid*33 + jj] + __ldg(bias + jj);
        }
    }
}

// ------------------------- per-(region,channel) stats -> scale/shift -------------------------
__global__ void stats_kernel(const float* __restrict__ gamma, const float* __restrict__ beta) {
    int rc = blockIdx.x;
    int region = rc >> 5;
    int c  = rc & 31;
    int ri = region >> 2, ci = region & 3;
    int tid = threadIdx.x;

    double s = 0.0, ss = 0.0;
    for (int i = tid; i < 64 * 1600; i += 256) {
        int b = i / 1600;
        int p = i - b * 1600;
        int y = ri * 40 + p / 40;
        int xx = ci * 40 + (p % 40);
        float v = g_bufA[((b * 32 + c) * 160 + y) * 160 + xx];
        s += (double)v; ss += (double)v * (double)v;
    }
    __shared__ double sh_s[256], sh_ss[256];
    sh_s[tid] = s; sh_ss[tid] = ss;
    __syncthreads();
    for (int off = 128; off > 0; off >>= 1) {
        if (tid < off) { sh_s[tid] += sh_s[tid + off]; sh_ss[tid] += sh_ss[tid + off]; }
        __syncthreads();
    }
    if (tid == 0) {
        double mean = sh_s[0] / 102400.0;
        double var  = sh_ss[0] / 102400.0 - mean * mean;
        float sc = __ldg(gamma + c) * rsqrtf((float)var + 1e-5f);
        g_scale[rc] = sc;
        g_shift[rc] = __ldg(beta + c) - (float)mean * sc;
    }
}

// ------------------------- rconv: warp-specialized, N=32, K=320 -------------------------
__global__ void __launch_bounds__(256) rconv_mma(const float* __restrict__ bias) {
    extern __shared__ char smem[];
    uint32_t sb = smem_u32(smem);
    int tid = threadIdx.x, wid = tid >> 5, lane = tid & 31;
    bool prod = tid >= 128;
    int ptid = tid & 127;

    int p  = blockIdx.x * 128 + ptid;
    int xo = p % 160, yo = (p / 160) % 160, b = p / 25600;
    int lx = xo % 40, ly = yo % 40;
    const uint32_t* ain = g_actHL + b * 819200 + yo * 160 + xo;

    int ry = ((ly > 0) ? 1 : 0) | 2 | ((ly < 39) ? 4 : 0);
    int cx = ((lx > 0) ? 1 : 0) | 2 | ((lx < 39) ? 4 : 0);
    int mask = 0;
#pragma unroll
    for (int ty = 0; ty < 3; ty++)
#pragma unroll
        for (int tx = 0; tx < 3; tx++)
            if (((ry >> ty) & 1) && ((cx >> tx) & 1)) mask |= 1 << (ty*3 + tx);

    float acc[32];
#pragma unroll
    for (int i = 0; i < 32; i++) acc[i] = 0.f;

    if (prod) rc_fill(smem, ain, mask, 0, ptid);
    __syncthreads();
    for (int c = 0; c < 5; c++) {
        if (prod) { if (c + 1 < 5) rc_fill(smem + ((c+1)&1)*BUFSZ_N32, ain, mask, (c+1)*64, ptid); }
        else      mma_chunk_n32(sb + (c&1)*BUFSZ_N32, wid, lane, acc);
        __syncthreads();
    }
    float* stg = (float*)smem;
    if (!prod) {
#pragma unroll
        for (int mt = 0; mt < 2; mt++)
#pragma unroll
            for (int nt = 0; nt < 4; nt++)
#pragma unroll
                for (int r = 0; r < 4; r++) {
                    int row = wid*32 + mt*16 + (lane >> 2) + ((r >> 1) << 3);
                    int col = nt*8 + ((lane & 3) << 1) + (r & 1);
                    stg[row*33 + col] = acc[(mt*4 + nt)*4 + r];
                }
    }
    __syncthreads();
    {
        float* op = g_bufB + (b * 32 * 160 + yo) * 160 + xo;
        int j0 = (tid >> 7) * 16;
#pragma unroll
        for (int j = 0; j < 16; j++) {
            int jj = j0 + j;
            op[jj * 25600] = stg[ptid*33 + jj] + __ldg(bias + jj);
        }
    }
}

// ------------------------- 2x2 maxpool, 160->80, fused split -------------------------
__global__ void pool_kernel() {
    int t = blockIdx.x * blockDim.x + threadIdx.x;
    if (t >= BATCH * 32 * 80 * 80) return;
    int xx = t % 80;
    int y  = (t / 80) % 80;
    int bc = t / 6400;
    const float* p = g_bufB + (bc * 160 + 2 * y) * 160 + 2 * xx;
    g_poolHL[t] = packHL(fmaxf(fmaxf(p[0], p[1]), fmaxf(p[160], p[161])));
}

// ------------------------- conv4: warp-specialized, N=16, K=2048 -------------------------
#define CONV4_M (BATCH * 73 * 73)
__global__ void __launch_bounds__(256) conv4_mma(const float* __restrict__ bias) {
    extern __shared__ char smem[];
    uint32_t sb = smem_u32(smem);
    int tid = threadIdx.x, wid = tid >> 5, lane = tid & 31;
    bool prod = tid >= 128;
    int ptid = tid & 127;

    int p  = blockIdx.x * 128 + ptid;
    bool pv = p < CONV4_M;
    int pp = pv ? p : 0;
    int xo = pp % 73, yo = (pp / 73) % 73, b = pp / 5329;
    const uint32_t* pin = g_poolHL + b * 204800 + yo * 80 + xo;

    float acc[16];
#pragma unroll
    for (int i = 0; i < 16; i++) acc[i] = 0.f;

    if (prod) c4_fill(smem, pin, pv, 0, ptid);
    __syncthreads();
    for (int c = 0; c < 32; c++) {
        if (prod) { if (c + 1 < 32) c4_fill(smem + ((c+1)&1)*BUFSZ_N16, pin, pv, (c+1)*64, ptid); }
        else      mma_chunk_n16(sb + (c&1)*BUFSZ_N16, wid, lane, acc);
        __syncthreads();
    }
    float* stg = (float*)smem;
    if (!prod) {
#pragma unroll
        for (int mt = 0; mt < 2; mt++)
#pragma unroll
            for (int nt = 0; nt < 2; nt++)
#pragma unroll
                for (int r = 0; r < 4; r++) {
                    int row = wid*32 + mt*16 + (lane >> 2) + ((r >> 1) << 3);
                    int col = nt*8 + ((lane & 3) << 1) + (r & 1);
                    stg[row*17 + col] = acc[(mt*2 + nt)*4 + r];
                }
    }
    __syncthreads();
    if (pv) {
        float* op = g_c4 + (b * 16 * 73 + yo) * 73 + xo;
        int j0 = (tid >> 7) * 8;
#pragma unroll
        for (int j = 0; j < 8; j++) {
            int jj = j0 + j;
            op[jj * 5329] = stg[ptid*17 + jj] + __ldg(bias + jj);
        }
    }
}

// ------------------------- weight transpose for remaining direct convs -------------------------
#define DEFINE_TRANS(NAME, OC, R, DST)                                        \
__global__ void NAME(const float* __restrict__ w) {                           \
    int e = blockIdx.x * blockDim.x + threadIdx.x;                            \
    if (e < (OC)*(R)) {                                                       \
        int oc = e / (R);                                                     \
        int r  = e - oc * (R);                                                \
        DST[r*(OC) + oc] = w[e];                                              \
    }                                                                         \
}
DEFINE_TRANS(t_w5,  16, 1024, g_wT5)
DEFINE_TRANS(t_w6,  16,  576, g_wT6)
DEFINE_TRANS(t_w7,  16,  400, g_wT7)
DEFINE_TRANS(t_w8,  16,  144, g_wT8)
DEFINE_TRANS(t_wfc, 512, 1024, g_wTfc)

// ------------------------- generic OC=16 direct conv, 2 pixels/thread -------------------------
#define DEFINE_CONV16(NAME, IC, K, S, IH, IW, OH, OW, INBUF, WTBUF, OUTBUF)          \
__global__ void __launch_bounds__(128) NAME(const float* __restrict__ bias) {        \
    const int XP  = ((OW) + 1) / 2;                                                  \
    const int OFF = (OW) - XP;                                                       \
    int t = blockIdx.x * 128 + threadIdx.x;                                          \
    if (t >= BATCH * (OH) * XP) return;                                              \
    int xo = t % XP;                                                                 \
    int yo = (t / XP) % (OH);                                                        \
    int b  = t / (XP * (OH));                                                        \
    float a0[16], a1[16];                                                            \
    _Pragma("unroll")                                                                \
    for (int j = 0; j < 16; j++) { float bv = __ldg(bias + j); a0[j] = bv; a1[j] = bv; } \
    for (int ic = 0; ic < (IC); ic++) {                                              \
        const float* inp = INBUF + ((b*(IC) + ic)*(IH) + yo*(S))*(IW) + xo*(S);      \
        _Pragma("unroll 1")                                                          \
        for (int ky = 0; ky < (K); ky++) {                                           \
            const float* row = inp + ky*(IW);                                        \
            const float4* wrow = (const float4*)(WTBUF + (ic*(K)*(K) + ky*(K))*16);  \
            _Pragma("unroll")                                                        \
            for (int kx = 0; kx < (K); kx++) {                                       \
                float v0 = __ldg(row + kx);                                          \
                float v1 = __ldg(row + OFF*(S) + kx);                                \
                _Pragma("unroll")                                                    \
                for (int j = 0; j < 4; j++) {                                        \
                    float4 w4 = __ldg(wrow + kx*4 + j);                              \
                    a0[4*j+0] = fmaf(v0, w4.x, a0[4*j+0]); a1[4*j+0] = fmaf(v1, w4.x, a1[4*j+0]); \
                    a0[4*j+1] = fmaf(v0, w4.y, a0[4*j+1]); a1[4*j+1] = fmaf(v1, w4.y, a1[4*j+1]); \
                    a0[4*j+2] = fmaf(v0, w4.z, a0[4*j+2]); a1[4*j+2] = fmaf(v1, w4.z, a1[4*j+2]); \
                    a0[4*j+3] = fmaf(v0, w4.w, a0[4*j+3]); a1[4*j+3] = fmaf(v1, w4.w, a1[4*j+3]); \
                }                                                                    \
            }                                                                        \
        }                                                                            \
    }                                                                                \
    float* op = OUTBUF + (b*16*(OH) + yo)*(OW) + xo;                                 \
    _Pragma("unroll")                                                                \
    for (int j = 0; j < 16; j++) {                                                   \
        op[j*(OH)*(OW)]       = a0[j];                                               \
        op[j*(OH)*(OW) + OFF] = a1[j];                                               \
    }                                                                                \
}

DEFINE_CONV16(conv5_kernel, 16, 8, 2, 73, 73, 33, 33, g_c4, g_wT5, g_c5)
DEFINE_CONV16(conv6_kernel, 16, 6, 1, 33, 33, 28, 28, g_c5, g_wT6, g_c6)
DEFINE_CONV16(conv7_kernel, 16, 5, 1, 28, 28, 24, 24, g_c6, g_wT7, g_c7)
DEFINE_CONV16(conv8_kernel, 16, 3, 3, 24, 24,  8,  8, g_c7, g_wT8, g_c8)

// ------------------------- FC -------------------------
__global__ void fc_kernel(const float* __restrict__ bias, float* __restrict__ out) {
    __shared__ float sm[1024];
    int b = blockIdx.x;
    int o = threadIdx.x;
    sm[o]       = g_c8[b * 1024 + o];
    sm[o + 512] = g_c8[b * 1024 + o + 512];
    __syncthreads();
    float acc = __ldg(bias + o);
#pragma unroll 4
    for (int k = 0; k < 1024; k++)
        acc = fmaf(sm[k], g_wTfc[k * 512 + o], acc);
    out[b * 512 + o] = acc;
}

// ------------------------- launch -------------------------
static inline int gridFor(long n, int bs) { return (int)((n + bs - 1) / bs); }

extern "C" void kernel_launch(void* const* d_in, const int* in_sizes, int n_in,
                              void* d_out, int out_size) {
    const float* x        = (const float*)d_in[0];
    const float* conv1_w  = (const float*)d_in[1];
    const float* conv1_b  = (const float*)d_in[2];
    const float* bn_gamma = (const float*)d_in[3];
    const float* bn_beta  = (const float*)d_in[4];
    const float* prelu_a  = (const float*)d_in[5];
    const float* rconv_w  = (const float*)d_in[6];
    const float* rconv_b  = (const float*)d_in[7];
    const float* conv4_w  = (const float*)d_in[8];
    const float* conv4_b  = (const float*)d_in[9];
    const float* conv5_b  = (const float*)d_in[11];
    const float* conv6_b  = (const float*)d_in[13];
    const float* conv7_b  = (const float*)d_in[15];
    const float* conv8_b  = (const float*)d_in[17];
    const float* fc_b     = (const float*)d_in[19];
    float* out = (float*)d_out;

    // opt-in to >48KB dynamic smem (idempotent, not an allocation)
    cudaFuncSetAttribute(conv1_mma, cudaFuncAttributeMaxDynamicSharedMemorySize, 2*BUFSZ_N32);
    cudaFuncSetAttribute(rconv_mma, cudaFuncAttributeMaxDynamicSharedMemorySize, 2*BUFSZ_N32);
    cudaFuncSetAttribute(conv4_mma, cudaFuncAttributeMaxDynamicSharedMemorySize, 2*BUFSZ_N16);

    // launches ordered so conv1_mma is the 4th launch (ncu captures launch #4)
    split_x<<<gridFor((long)BATCH*3*170*170, 256), 256>>>(x);
    t_w1hl<<<gridFor(32*384, 256), 256>>>(conv1_w);
    t_wrhl<<<gridFor(32*320, 256), 256>>>(rconv_w);
    conv1_mma<<<12800, 256, 2*BUFSZ_N32>>>(conv1_b);

    t_w4hl<<<gridFor(16*2048, 256), 256>>>(conv4_w);
    t_w5 <<<gridFor(16*1024, 256), 256>>>((const float*)d_in[10]);
    t_w6 <<<gridFor(16*576,  256), 256>>>((const float*)d_in[12]);
    t_w7 <<<gridFor(16*400,  256), 256>>>((const float*)d_in[14]);
    t_w8 <<<gridFor(16*144,  256), 256>>>((const float*)d_in[16]);
    t_wfc<<<gridFor(512*1024,256), 256>>>((const float*)d_in[18]);

    stats_kernel<<<512, 256>>>(bn_gamma, bn_beta);
    act_kernel<<<gridFor((long)BATCH*32*160*160, 256), 256>>>(prelu_a);
    rconv_mma<<<12800, 256, 2*BUFSZ_N32>>>(rconv_b);
    pool_kernel<<<gridFor((long)BATCH*32*80*80, 256), 256>>>();

    conv4_mma<<<gridFor(CONV4_M, 128), 256, 2*BUFSZ_N16>>>(conv4_b);
    conv5_kernel<<<gridFor((long)BATCH*33*17, 128), 128>>>(conv5_b);
    conv6_kernel<<<gridFor((long)BATCH*28*14, 128), 128>>>(conv6_b);
    conv7_kernel<<<gridFor((long)BATCH*24*12, 128), 128>>>(conv7_b);
    conv8_kernel<<<gridFor((long)BATCH*8*4,   128), 128>>>(conv8_b);

    fc_kernel<<<BATCH, 512>>>(fc_b, out);
}

// round 6
// speedup vs baseline: 1.5665x; 1.5665x over previous
#include <cuda_runtime.h>
#include <cuda_bf16.h>
#include <cstdint>

#define BATCH 64

// ------------------------- scratch (no allocs allowed) -------------------------
__device__ float    g_bufA[BATCH*32*160*160];   // conv1 out (fp32, for stats)
__device__ float    g_bufB[BATCH*32*160*160];   // rconv out (fp32, for pool)
__device__ uint32_t g_xHL[BATCH*3*170*170];     // input, packed hi/lo bf16
__device__ uint32_t g_actHL[BATCH*32*160*160];  // norm+PReLU(conv1 out), packed
__device__ uint32_t g_poolHL[BATCH*32*80*80];   // pooled, packed
__device__ float g_c4[BATCH*16*73*73];
__device__ float g_c5[BATCH*16*33*33];
__device__ float g_c6[BATCH*16*28*28];
__device__ float g_c7[BATCH*16*24*24];
__device__ float g_c8[BATCH*16*8*8];

__device__ uint32_t g_w1HL[32*384];    // conv1 w, K padded 363->384
__device__ uint32_t g_wrHL[32*320];    // rconv w, reordered k=t*32+ic, padded 288->320
__device__ uint32_t g_w4HL[16*2048];   // conv4 w

__device__ float g_wT5[1024*16];
__device__ float g_wT6[576*16];
__device__ float g_wT7[400*16];
__device__ float g_wT8[144*16];
__device__ float g_wTfc[1024*512];

__device__ float g_scale[512];   // [region(16)][channel(32)]
__device__ float g_shift[512];

// ------------------------- helpers -------------------------
__device__ __forceinline__ uint32_t smem_u32(const void* p) {
    uint32_t a;
    asm("{ .reg .u64 t; cvta.to.shared.u64 t, %1; cvt.u32.u64 %0, t; }" : "=r"(a) : "l"(p));
    return a;
}
__device__ __forceinline__ uint32_t sw128(uint32_t o) { return o ^ ((o >> 3) & 0x70); }

__device__ __forceinline__ uint32_t packHL(float v) {
    __nv_bfloat16 h = __float2bfloat16(v);
    float r = v - __bfloat162float(h);
    __nv_bfloat16 l = __float2bfloat16(r);
    uint16_t hb = *reinterpret_cast<uint16_t*>(&h);
    uint16_t lb = *reinterpret_cast<uint16_t*>(&l);
    return (uint32_t)hb | ((uint32_t)lb << 16);
}

__device__ __forceinline__ void ldsm4(uint32_t* r, uint32_t addr) {
    asm volatile("ldmatrix.sync.aligned.m8n8.x4.shared.b16 {%0,%1,%2,%3}, [%4];"
                 : "=r"(r[0]), "=r"(r[1]), "=r"(r[2]), "=r"(r[3]) : "r"(addr));
}

__device__ __forceinline__ void mma_bf16(float* c,
        uint32_t a0, uint32_t a1, uint32_t a2, uint32_t a3,
        uint32_t b0, uint32_t b1) {
    asm volatile(
        "mma.sync.aligned.m16n8k16.row.col.f32.bf16.bf16.f32 "
        "{%0,%1,%2,%3}, {%4,%5,%6,%7}, {%8,%9}, {%0,%1,%2,%3};"
        : "+f"(c[0]), "+f"(c[1]), "+f"(c[2]), "+f"(c[3])
        : "r"(a0), "r"(a1), "r"(a2), "r"(a3), "r"(b0), "r"(b1));
}

// ------------------- smem layout (M=256 tiles, single buffer) -------------------
#define A_HI 0
#define A_LO 32768
#define B_HI 65536
#define B_LO 69632
#define SM_N32 73728
#define C4B_HI 65536
#define C4B_LO 67584
#define SM_N16 69632

// consumer: 4 k-steps of one 64-wide K chunk, N=32, warp handles rows wid*32..+31
__device__ __forceinline__ void mma_chunk_n32(uint32_t sb, int wid, int lane, float* acc) {
#pragma unroll
    for (int ks = 0; ks < 4; ks++) {
        uint32_t a_hi[8], a_lo[8], b_hi[8], b_lo[8];
        uint32_t abyte = (uint32_t)((wid*32 + (lane & 15))*128 + (ks*16 + ((lane >> 4) << 3))*2);
        ldsm4(&a_hi[0], sb + A_HI + sw128(abyte));
        ldsm4(&a_hi[4], sb + A_HI + sw128(abyte) + 2048);
        ldsm4(&a_lo[0], sb + A_LO + sw128(abyte));
        ldsm4(&a_lo[4], sb + A_LO + sw128(abyte) + 2048);
        uint32_t bbyte = (uint32_t)(((((lane >> 4) << 3) + (lane & 7))*128) + (ks*16 + (lane & 8))*2);
        ldsm4(&b_hi[0], sb + B_HI + sw128(bbyte));
        ldsm4(&b_hi[4], sb + B_HI + sw128(bbyte) + 2048);
        ldsm4(&b_lo[0], sb + B_LO + sw128(bbyte));
        ldsm4(&b_lo[4], sb + B_LO + sw128(bbyte) + 2048);
#pragma unroll
        for (int mt = 0; mt < 2; mt++) {
#pragma unroll
            for (int nt = 0; nt < 4; nt++) {
                float* cc = acc + (mt*4 + nt)*4;
                const uint32_t* A  = a_hi + mt*4;
                const uint32_t* Al = a_lo + mt*4;
                uint32_t bh0 = b_hi[nt*2], bh1 = b_hi[nt*2+1];
                uint32_t bl0 = b_lo[nt*2], bl1 = b_lo[nt*2+1];
                mma_bf16(cc, A[0],A[1],A[2],A[3],   bh0, bh1);
                mma_bf16(cc, Al[0],Al[1],Al[2],Al[3], bh0, bh1);
                mma_bf16(cc, A[0],A[1],A[2],A[3],   bl0, bl1);
            }
        }
    }
}

// consumer: N=16 variant (conv4)
__device__ __forceinline__ void mma_chunk_n16(uint32_t sb, int wid, int lane, float* acc) {
#pragma unroll
    for (int ks = 0; ks < 4; ks++) {
        uint32_t a_hi[8], a_lo[8], b_hi[4], b_lo[4];
        uint32_t abyte = (uint32_t)((wid*32 + (lane & 15))*128 + (ks*16 + ((lane >> 4) << 3))*2);
        ldsm4(&a_hi[0], sb + A_HI + sw128(abyte));
        ldsm4(&a_hi[4], sb + A_HI + sw128(abyte) + 2048);
        ldsm4(&a_lo[0], sb + A_LO + sw128(abyte));
        ldsm4(&a_lo[4], sb + A_LO + sw128(abyte) + 2048);
        uint32_t bbyte = (uint32_t)(((((lane >> 4) << 3) + (lane & 7))*128) + (ks*16 + (lane & 8))*2);
        ldsm4(b_hi, sb + C4B_HI + sw128(bbyte));
        ldsm4(b_lo, sb + C4B_LO + sw128(bbyte));
#pragma unroll
        for (int mt = 0; mt < 2; mt++) {
#pragma unroll
            for (int nt = 0; nt < 2; nt++) {
                float* cc = acc + (mt*2 + nt)*4;
                const uint32_t* A  = a_hi + mt*4;
                const uint32_t* Al = a_lo + mt*4;
                uint32_t bh0 = b_hi[nt*2], bh1 = b_hi[nt*2+1];
                uint32_t bl0 = b_lo[nt*2], bl1 = b_lo[nt*2+1];
                mma_bf16(cc, A[0],A[1],A[2],A[3],   bh0, bh1);
                mma_bf16(cc, Al[0],Al[1],Al[2],Al[3], bh0, bh1);
                mma_bf16(cc, A[0],A[1],A[2],A[3],   bl0, bl1);
            }
        }
    }
}

// store 4 gathered HL words as hi/lo STS.64 pair
__device__ __forceinline__ void sts_quad(char* buf, int tid, int j,
                                         uint32_t v0, uint32_t v1, uint32_t v2, uint32_t v3) {
    uint32_t off = sw128((uint32_t)(tid * 128 + j * 8));
    uint2 h; h.x = __byte_perm(v0, v1, 0x5410); h.y = __byte_perm(v2, v3, 0x5410);
    uint2 l; l.x = __byte_perm(v0, v1, 0x7632); l.y = __byte_perm(v2, v3, 0x7632);
    *(uint2*)(buf + A_HI + off) = h;
    *(uint2*)(buf + A_LO + off) = l;
}

// ------------------------- pre-pass kernels -------------------------
__global__ void split_x(const float* __restrict__ x) {
    int t = blockIdx.x * blockDim.x + threadIdx.x;
    if (t < BATCH*3*170*170) g_xHL[t] = packHL(x[t]);
}
__global__ void t_w1hl(const float* __restrict__ w) {
    int e = blockIdx.x * blockDim.x + threadIdx.x;
    if (e < 32*384) {
        int oc = e / 384, k = e - oc*384;
        g_w1HL[e] = (k < 363) ? packHL(w[oc*363 + k]) : 0u;
    }
}
__global__ void t_wrhl(const float* __restrict__ w) {
    int e = blockIdx.x * blockDim.x + threadIdx.x;
    if (e < 32*320) {
        int oc = e / 320, k = e - oc*320;
        int t9 = k >> 5, ic = k & 31;
        g_wrHL[e] = (t9 < 9) ? packHL(w[oc*288 + ic*9 + t9]) : 0u;
    }
}
__global__ void t_w4hl(const float* __restrict__ w) {
    int e = blockIdx.x * blockDim.x + threadIdx.x;
    if (e < 16*2048) g_w4HL[e] = packHL(w[e]);
}

// norm + PReLU + split, one pass
__global__ void act_kernel(const float* __restrict__ pa) {
    int t = blockIdx.x * blockDim.x + threadIdx.x;
    if (t >= BATCH*32*160*160) return;
    int xx = t % 160;
    int y  = (t / 160) % 160;
    int c  = (t / 25600) % 32;
    int region = (y / 40) * 4 + (xx / 40);
    float v = g_bufA[t];
    float r = fmaf(v, g_scale[region*32 + c], g_shift[region*32 + c]);
    float a = __ldg(pa);
    g_actHL[t] = packHL((r > 0.0f) ? r : a * r);
}

// ------------------------- conv1: implicit GEMM, M=256 pix, N=32, K=384 -------------------------
__global__ void __launch_bounds__(256) conv1_mma(const float* __restrict__ bias) {
    extern __shared__ char smem[];
    __shared__ __align__(16) int soffs[384];
    uint32_t sb = smem_u32(smem);
    int tid = threadIdx.x, wid = tid >> 5, lane = tid & 31;

    for (int k = tid; k < 384; k += 256) {
        if (k < 363) {
            int ic = k / 121;
            int r  = k - ic * 121;
            int ky = r / 11, kx = r - ky * 11;
            soffs[k] = ic * 28900 + ky * 170 + kx;
        } else soffs[k] = -1;
    }

    int p  = blockIdx.x * 256 + tid;
    int xo = p % 160, yo = (p / 160) % 160, b = p / 25600;
    const uint32_t* xin = g_xHL + b * 86700 + yo * 170 + xo;

    float acc[32];
#pragma unroll
    for (int i = 0; i < 32; i++) acc[i] = 0.f;
    __syncthreads();

    for (int c = 0; c < 6; c++) {
        int k0 = c * 64;
#pragma unroll 4
        for (int j = 0; j < 16; j++) {
            int4 o4 = *(const int4*)(soffs + k0 + 4*j);
            uint32_t v0 = (o4.x >= 0) ? __ldg(xin + o4.x) : 0u;
            uint32_t v1 = (o4.y >= 0) ? __ldg(xin + o4.y) : 0u;
            uint32_t v2 = (o4.z >= 0) ? __ldg(xin + o4.z) : 0u;
            uint32_t v3 = (o4.w >= 0) ? __ldg(xin + o4.w) : 0u;
            sts_quad(smem, tid, j, v0, v1, v2, v3);
        }
#pragma unroll
        for (int e = tid; e < 1024; e += 256) {
            int oc = e >> 5, i = e & 31;
            uint2 w2 = __ldg((const uint2*)(g_w1HL + oc*384 + k0 + 2*i));
            uint32_t off = sw128((uint32_t)(oc * 128 + i * 4));
            *(uint32_t*)(smem + B_HI + off) = __byte_perm(w2.x, w2.y, 0x5410);
            *(uint32_t*)(smem + B_LO + off) = __byte_perm(w2.x, w2.y, 0x7632);
        }
        __syncthreads();
        mma_chunk_n32(sb, wid, lane, acc);
        __syncthreads();
    }
    // two-phase epilogue
    float* stg = (float*)smem;
#pragma unroll
    for (int h = 0; h < 2; h++) {
        if ((wid >> 2) == h) {
#pragma unroll
            for (int mt = 0; mt < 2; mt++)
#pragma unroll
                for (int nt = 0; nt < 4; nt++)
#pragma unroll
                    for (int r = 0; r < 4; r++) {
                        int row = (wid & 3)*32 + mt*16 + (lane >> 2) + ((r >> 1) << 3);
                        int col = nt*8 + ((lane & 3) << 1) + (r & 1);
                        stg[row*33 + col] = acc[(mt*4 + nt)*4 + r];
                    }
        }
        __syncthreads();
        {
            int r  = tid & 127;
            int j0 = (tid >> 7) * 16;
            int pp = blockIdx.x * 256 + h * 128 + r;
            int xo2 = pp % 160, yo2 = (pp / 160) % 160, b2 = pp / 25600;
            float* op = g_bufA + (b2 * 32 * 160 + yo2) * 160 + xo2;
#pragma unroll
            for (int j = 0; j < 16; j++) {
                int jj = j0 + j;
                op[jj * 25600] = stg[r*33 + jj] + __ldg(bias + jj);
            }
        }
        __syncthreads();
    }
}

// ------------------------- per-(region,channel) stats -> scale/shift -------------------------
__global__ void stats_kernel(const float* __restrict__ gamma, const float* __restrict__ beta) {
    int rc = blockIdx.x;
    int region = rc >> 5;
    int c  = rc & 31;
    int ri = region >> 2, ci = region & 3;
    int tid = threadIdx.x;

    double s = 0.0, ss = 0.0;
    for (int i = tid; i < 64 * 1600; i += 256) {
        int b = i / 1600;
        int p = i - b * 1600;
        int y = ri * 40 + p / 40;
        int xx = ci * 40 + (p % 40);
        float v = g_bufA[((b * 32 + c) * 160 + y) * 160 + xx];
        s += (double)v; ss += (double)v * (double)v;
    }
    __shared__ double sh_s[256], sh_ss[256];
    sh_s[tid] = s; sh_ss[tid] = ss;
    __syncthreads();
    for (int off = 128; off > 0; off >>= 1) {
        if (tid < off) { sh_s[tid] += sh_s[tid + off]; sh_ss[tid] += sh_ss[tid + off]; }
        __syncthreads();
    }
    if (tid == 0) {
        double mean = sh_s[0] / 102400.0;
        double var  = sh_ss[0] / 102400.0 - mean * mean;
        float sc = __ldg(gamma + c) * rsqrtf((float)var + 1e-5f);
        g_scale[rc] = sc;
        g_shift[rc] = __ldg(beta + c) - (float)mean * sc;
    }
}

// ------------------------- rconv: implicit GEMM, M=256, N=32, K=320 -------------------------
__global__ void __launch_bounds__(256) rconv_mma(const float* __restrict__ bias) {
    extern __shared__ char smem[];
    uint32_t sb = smem_u32(smem);
    int tid = threadIdx.x, wid = tid >> 5, lane = tid & 31;

    int p  = blockIdx.x * 256 + tid;
    int xo = p % 160, yo = (p / 160) % 160, b = p / 25600;
    int lx = xo % 40, ly = yo % 40;
    const uint32_t* ain = g_actHL + b * 819200 + yo * 160 + xo;

    int ry = ((ly > 0) ? 1 : 0) | 2 | ((ly < 39) ? 4 : 0);
    int cx = ((lx > 0) ? 1 : 0) | 2 | ((lx < 39) ? 4 : 0);
    int mask = 0;
#pragma unroll
    for (int ty = 0; ty < 3; ty++)
#pragma unroll
        for (int tx = 0; tx < 3; tx++)
            if (((ry >> ty) & 1) && ((cx >> tx) & 1)) mask |= 1 << (ty*3 + tx);

    float acc[32];
#pragma unroll
    for (int i = 0; i < 32; i++) acc[i] = 0.f;

    for (int c = 0; c < 5; c++) {
        int k0 = c * 64;
#pragma unroll 4
        for (int j = 0; j < 16; j++) {
            int k  = k0 + 4 * j;
            int t  = k >> 5;
            int ic = k & 31;
            uint32_t v0 = 0u, v1 = 0u, v2 = 0u, v3 = 0u;
            if (t < 9 && ((mask >> t) & 1)) {
                int ty = t / 3;
                int dd = (ty - 1) * 160 + (t - ty * 3 - 1);
                const uint32_t* q = ain + ic * 25600 + dd;
                v0 = __ldg(q);
                v1 = __ldg(q + 25600);
                v2 = __ldg(q + 51200);
                v3 = __ldg(q + 76800);
            }
            sts_quad(smem, tid, j, v0, v1, v2, v3);
        }
#pragma unroll
        for (int e = tid; e < 1024; e += 256) {
            int oc = e >> 5, i = e & 31;
            uint2 w2 = __ldg((const uint2*)(g_wrHL + oc*320 + k0 + 2*i));
            uint32_t off = sw128((uint32_t)(oc * 128 + i * 4));
            *(uint32_t*)(smem + B_HI + off) = __byte_perm(w2.x, w2.y, 0x5410);
            *(uint32_t*)(smem + B_LO + off) = __byte_perm(w2.x, w2.y, 0x7632);
        }
        __syncthreads();
        mma_chunk_n32(sb, wid, lane, acc);
        __syncthreads();
    }
    float* stg = (float*)smem;
#pragma unroll
    for (int h = 0; h < 2; h++) {
        if ((wid >> 2) == h) {
#pragma unroll
            for (int mt = 0; mt < 2; mt++)
#pragma unroll
                for (int nt = 0; nt < 4; nt++)
#pragma unroll
                    for (int r = 0; r < 4; r++) {
                        int row = (wid & 3)*32 + mt*16 + (lane >> 2) + ((r >> 1) << 3);
                        int col = nt*8 + ((lane & 3) << 1) + (r & 1);
                        stg[row*33 + col] = acc[(mt*4 + nt)*4 + r];
                    }
        }
        __syncthreads();
        {
            int r  = tid & 127;
            int j0 = (tid >> 7) * 16;
            int pp = blockIdx.x * 256 + h * 128 + r;
            int xo2 = pp % 160, yo2 = (pp / 160) % 160, b2 = pp / 25600;
            float* op = g_bufB + (b2 * 32 * 160 + yo2) * 160 + xo2;
#pragma unroll
            for (int j = 0; j < 16; j++) {
                int jj = j0 + j;
                op[jj * 25600] = stg[r*33 + jj] + __ldg(bias + jj);
            }
        }
        __syncthreads();
    }
}

// ------------------------- 2x2 maxpool, 160->80, fused split -------------------------
__global__ void pool_kernel() {
    int t = blockIdx.x * blockDim.x + threadIdx.x;
    if (t >= BATCH * 32 * 80 * 80) return;
    int xx = t % 80;
    int y  = (t / 80) % 80;
    int bc = t / 6400;
    const float* p = g_bufB + (bc * 160 + 2 * y) * 160 + 2 * xx;
    g_poolHL[t] = packHL(fmaxf(fmaxf(p[0], p[1]), fmaxf(p[160], p[161])));
}

// ------------------------- conv4: implicit GEMM, M=256, N=16, K=2048 -------------------------
#define CONV4_M (BATCH * 73 * 73)
__global__ void __launch_bounds__(256) conv4_mma(const float* __restrict__ bias) {
    extern __shared__ char smem[];
    uint32_t sb = smem_u32(smem);
    int tid = threadIdx.x, wid = tid >> 5, lane = tid & 31;

    int p  = blockIdx.x * 256 + tid;
    bool pv = p < CONV4_M;
    int pp = pv ? p : 0;
    int xo = pp % 73, yo = (pp / 73) % 73, b = pp / 5329;
    const uint32_t* pin = g_poolHL + b * 204800 + yo * 80 + xo;

    float acc[16];
#pragma unroll
    for (int i = 0; i < 16; i++) acc[i] = 0.f;

    for (int c = 0; c < 32; c++) {
        int k0 = c * 64;
#pragma unroll 4
        for (int j = 0; j < 16; j++) {
            int k  = k0 + 4 * j;
            int ic = k >> 6;
            int r  = k & 63;
            int ky = r >> 3, kx = r & 7;   // kx in {0,4}
            uint32_t v0 = 0u, v1 = 0u, v2 = 0u, v3 = 0u;
            if (pv) {
                const uint32_t* q = pin + ic * 6400 + ky * 80 + kx;
                v0 = __ldg(q);
                v1 = __ldg(q + 1);
                v2 = __ldg(q + 2);
                v3 = __ldg(q + 3);
            }
            sts_quad(smem, tid, j, v0, v1, v2, v3);
        }
#pragma unroll
        for (int e = tid; e < 512; e += 256) {
            int oc = e >> 5, i = e & 31;
            uint2 w2 = __ldg((const uint2*)(g_w4HL + oc*2048 + k0 + 2*i));
            uint32_t off = sw128((uint32_t)(oc * 128 + i * 4));
            *(uint32_t*)(smem + C4B_HI + off) = __byte_perm(w2.x, w2.y, 0x5410);
            *(uint32_t*)(smem + C4B_LO + off) = __byte_perm(w2.x, w2.y, 0x7632);
        }
        __syncthreads();
        mma_chunk_n16(sb, wid, lane, acc);
        __syncthreads();
    }
    float* stg = (float*)smem;
#pragma unroll
    for (int h = 0; h < 2; h++) {
        if ((wid >> 2) == h) {
#pragma unroll
            for (int mt = 0; mt < 2; mt++)
#pragma unroll
                for (int nt = 0; nt < 2; nt++)
#pragma unroll
                    for (int r = 0; r < 4; r++) {
                        int row = (wid & 3)*32 + mt*16 + (lane >> 2) + ((r >> 1) << 3);
                        int col = nt*8 + ((lane & 3) << 1) + (r & 1);
                        stg[row*17 + col] = acc[(mt*2 + nt)*4 + r];
                    }
        }
        __syncthreads();
        {
            int r  = tid & 127;
            int j0 = (tid >> 7) * 8;
            int pq = blockIdx.x * 256 + h * 128 + r;
            if (pq < CONV4_M) {
                int xo2 = pq % 73, yo2 = (pq / 73) % 73, b2 = pq / 5329;
                float* op = g_c4 + (b2 * 16 * 73 + yo2) * 73 + xo2;
#pragma unroll
                for (int j = 0; j < 8; j++) {
                    int jj = j0 + j;
                    op[jj * 5329] = stg[r*17 + jj] + __ldg(bias + jj);
                }
            }
        }
        __syncthreads();
    }
}

// ------------------------- weight transpose for remaining direct convs -------------------------
#define DEFINE_TRANS(NAME, OC, R, DST)                                        \
__global__ void NAME(const float* __restrict__ w) {                           \
    int e = blockIdx.x * blockDim.x + threadIdx.x;                            \
    if (e < (OC)*(R)) {                                                       \
        int oc = e / (R);                                                     \
        int r  = e - oc * (R);                                                \
        DST[r*(OC) + oc] = w[e];                                              \
    }                                                                         \
}
DEFINE_TRANS(t_w5,  16, 1024, g_wT5)
DEFINE_TRANS(t_w6,  16,  576, g_wT6)
DEFINE_TRANS(t_w7,  16,  400, g_wT7)
DEFINE_TRANS(t_w8,  16,  144, g_wT8)
DEFINE_TRANS(t_wfc, 512, 1024, g_wTfc)

// ------------------------- generic OC=16 direct conv, 2 pixels/thread -------------------------
#define DEFINE_CONV16(NAME, IC, K, S, IH, IW, OH, OW, INBUF, WTBUF, OUTBUF)          \
__global__ void __launch_bounds__(128) NAME(const float* __restrict__ bias) {        \
    const int XP  = ((OW) + 1) / 2;                                                  \
    const int OFF = (OW) - XP;                                                       \
    int t = blockIdx.x * 128 + threadIdx.x;                                          \
    if (t >= BATCH * (OH) * XP) return;                                              \
    int xo = t % XP;                                                                 \
    int yo = (t / XP) % (OH);                                                        \
    int b  = t / (XP * (OH));                                                        \
    float a0[16], a1[16];                                                            \
    _Pragma("unroll")                                                                \
    for (int j = 0; j < 16; j++) { float bv = __ldg(bias + j); a0[j] = bv; a1[j] = bv; } \
    for (int ic = 0; ic < (IC); ic++) {                                              \
        const float* inp = INBUF + ((b*(IC) + ic)*(IH) + yo*(S))*(IW) + xo*(S);      \
        _Pragma("unroll 1")                                                          \
        for (int ky = 0; ky < (K); ky++) {                                           \
            const float* row = inp + ky*(IW);                                        \
            const float4* wrow = (const float4*)(WTBUF + (ic*(K)*(K) + ky*(K))*16);  \
            _Pragma("unroll")                                                        \
            for (int kx = 0; kx < (K); kx++) {                                       \
                float v0 = __ldg(row + kx);                                          \
                float v1 = __ldg(row + OFF*(S) + kx);                                \
                _Pragma("unroll")                                                    \
                for (int j = 0; j < 4; j++) {                                        \
                    float4 w4 = __ldg(wrow + kx*4 + j);                              \
                    a0[4*j+0] = fmaf(v0, w4.x, a0[4*j+0]); a1[4*j+0] = fmaf(v1, w4.x, a1[4*j+0]); \
                    a0[4*j+1] = fmaf(v0, w4.y, a0[4*j+1]); a1[4*j+1] = fmaf(v1, w4.y, a1[4*j+1]); \
                    a0[4*j+2] = fmaf(v0, w4.z, a0[4*j+2]); a1[4*j+2] = fmaf(v1, w4.z, a1[4*j+2]); \
                    a0[4*j+3] = fmaf(v0, w4.w, a0[4*j+3]); a1[4*j+3] = fmaf(v1, w4.w, a1[4*j+3]); \
                }                                                                    \
            }                                                                        \
        }                                                                            \
    }                                                                                \
    float* op = OUTBUF + (b*16*(OH) + yo)*(OW) + xo;                                 \
    _Pragma("unroll")                                                                \
    for (int j = 0; j < 16; j++) {                                                   \
        op[j*(OH)*(OW)]       = a0[j];                                               \
        op[j*(OH)*(OW) + OFF] = a1[j];                                               \
    }                                                                                \
}

DEFINE_CONV16(conv5_kernel, 16, 8, 2, 73, 73, 33, 33, g_c4, g_wT5, g_c5)
DEFINE_CONV16(conv6_kernel, 16, 6, 1, 33, 33, 28, 28, g_c5, g_wT6, g_c6)
DEFINE_CONV16(conv7_kernel, 16, 5, 1, 28, 28, 24, 24, g_c6, g_wT7, g_c7)
DEFINE_CONV16(conv8_kernel, 16, 3, 3, 24, 24,  8,  8, g_c7, g_wT8, g_c8)

// ------------------------- FC -------------------------
__global__ void fc_kernel(const float* __restrict__ bias, float* __restrict__ out) {
    __shared__ float sm[1024];
    int b = blockIdx.x;
    int o = threadIdx.x;
    sm[o]       = g_c8[b * 1024 + o];
    sm[o + 512] = g_c8[b * 1024 + o + 512];
    __syncthreads();
    float acc = __ldg(bias + o);
#pragma unroll 4
    for (int k = 0; k < 1024; k++)
        acc = fmaf(sm[k], g_wTfc[k * 512 + o], acc);
    out[b * 512 + o] = acc;
}

// ------------------------- launch -------------------------
static inline int gridFor(long n, int bs) { return (int)((n + bs - 1) / bs); }

extern "C" void kernel_launch(void* const* d_in, const int* in_sizes, int n_in,
                              void* d_out, int out_size) {
    const float* x        = (const float*)d_in[0];
    const float* conv1_w  = (const float*)d_in[1];
    const float* conv1_b  = (const float*)d_in[2];
    const float* bn_gamma = (const float*)d_in[3];
    const float* bn_beta  = (const float*)d_in[4];
    const float* prelu_a  = (const float*)d_in[5];
    const float* rconv_w  = (const float*)d_in[6];
    const float* rconv_b  = (const float*)d_in[7];
    const float* conv4_w  = (const float*)d_in[8];
    const float* conv4_b  = (const float*)d_in[9];
    const float* conv5_b  = (const float*)d_in[11];
    const float* conv6_b  = (const float*)d_in[13];
    const float* conv7_b  = (const float*)d_in[15];
    const float* conv8_b  = (const float*)d_in[17];
    const float* fc_b     = (const float*)d_in[19];
    float* out = (float*)d_out;

    cudaFuncSetAttribute(conv1_mma, cudaFuncAttributeMaxDynamicSharedMemorySize, SM_N32);
    cudaFuncSetAttribute(rconv_mma, cudaFuncAttributeMaxDynamicSharedMemorySize, SM_N32);
    cudaFuncSetAttribute(conv4_mma, cudaFuncAttributeMaxDynamicSharedMemorySize, SM_N16);

    // launches ordered so conv1_mma is the 4th launch (ncu captures launch #4)
    split_x<<<gridFor((long)BATCH*3*170*170, 256), 256>>>(x);
    t_w1hl<<<gridFor(32*384, 256), 256>>>(conv1_w);
    t_wrhl<<<gridFor(32*320, 256), 256>>>(rconv_w);
    conv1_mma<<<6400, 256, SM_N32>>>(conv1_b);

    t_w4hl<<<gridFor(16*2048, 256), 256>>>(conv4_w);
    t_w5 <<<gridFor(16*1024, 256), 256>>>((const float*)d_in[10]);
    t_w6 <<<gridFor(16*576,  256), 256>>>((const float*)d_in[12]);
    t_w7 <<<gridFor(16*400,  256), 256>>>((const float*)d_in[14]);
    t_w8 <<<gridFor(16*144,  256), 256>>>((const float*)d_in[16]);
    t_wfc<<<gridFor(512*1024,256), 256>>>((const float*)d_in[18]);

    stats_kernel<<<512, 256>>>(bn_gamma, bn_beta);
    act_kernel<<<gridFor((long)BATCH*32*160*160, 256), 256>>>(prelu_a);
    rconv_mma<<<6400, 256, SM_N32>>>(rconv_b);
    pool_kernel<<<gridFor((long)BATCH*32*80*80, 256), 256>>>();

    conv4_mma<<<gridFor(CONV4_M, 256), 256, SM_N16>>>(conv4_b);
    conv5_kernel<<<gridFor((long)BATCH*33*17, 128), 128>>>(conv5_b);
    conv6_kernel<<<gridFor((long)BATCH*28*14, 128), 128>>>(conv6_b);
    conv7_kernel<<<gridFor((long)BATCH*24*12, 128), 128>>>(conv7_b);
    conv8_kernel<<<gridFor((long)BATCH*8*4,   128), 128>>>(conv8_b);

    fc_kernel<<<BATCH, 512>>>(fc_b, out);
}

// round 7
// speedup vs baseline: 1.6894x; 1.0784x over previous
#include <cuda_runtime.h>
#include <cuda_bf16.h>
#include <cstdint>

#define BATCH 64

// ------------------------- scratch (no allocs allowed) -------------------------
__device__ float    g_bufA[BATCH*32*160*160];   // conv1 out (fp32, for stats)
__device__ float    g_bufB[BATCH*32*160*160];   // rconv out (fp32, for pool)
__device__ uint32_t g_xHL[BATCH*3*170*170];     // input, packed hi/lo bf16
__device__ uint32_t g_actHL[BATCH*32*160*160];  // norm+PReLU(conv1 out), packed
__device__ uint32_t g_poolHL[BATCH*32*80*80];   // pooled, packed
__device__ float g_c4[BATCH*16*73*73];
__device__ float g_c5[BATCH*16*33*33];
__device__ float g_c6[BATCH*16*28*28];
__device__ float g_c7[BATCH*16*24*24];
__device__ float g_c8[BATCH*16*8*8];

__device__ uint32_t g_w1HL[32*384];    // conv1 w, K padded 363->384
__device__ uint32_t g_wrHL[32*320];    // rconv w, reordered k=t*32+ic, padded 288->320
__device__ uint32_t g_w4HL[16*2048];   // conv4 w

__device__ float g_wT5[1024*16];
__device__ float g_wT6[576*16];
__device__ float g_wT7[400*16];
__device__ float g_wT8[144*16];
__device__ float g_wTfc[1024*512];

__device__ float g_scale[512];   // [region(16)][channel(32)]
__device__ float g_shift[512];

// ------------------------- helpers -------------------------
__device__ __forceinline__ uint32_t smem_u32(const void* p) {
    uint32_t a;
    asm("{ .reg .u64 t; cvta.to.shared.u64 t, %1; cvt.u32.u64 %0, t; }" : "=r"(a) : "l"(p));
    return a;
}
__device__ __forceinline__ uint32_t sw128(uint32_t o) { return o ^ ((o >> 3) & 0x70); }

__device__ __forceinline__ uint32_t packHL(float v) {
    __nv_bfloat16 h = __float2bfloat16(v);
    float r = v - __bfloat162float(h);
    __nv_bfloat16 l = __float2bfloat16(r);
    uint16_t hb = *reinterpret_cast<uint16_t*>(&h);
    uint16_t lb = *reinterpret_cast<uint16_t*>(&l);
    return (uint32_t)hb | ((uint32_t)lb << 16);
}

__device__ __forceinline__ void ldsm4(uint32_t* r, uint32_t addr) {
    asm volatile("ldmatrix.sync.aligned.m8n8.x4.shared.b16 {%0,%1,%2,%3}, [%4];"
                 : "=r"(r[0]), "=r"(r[1]), "=r"(r[2]), "=r"(r[3]) : "r"(addr));
}

__device__ __forceinline__ void mma_bf16(float* c,
        uint32_t a0, uint32_t a1, uint32_t a2, uint32_t a3,
        uint32_t b0, uint32_t b1) {
    asm volatile(
        "mma.sync.aligned.m16n8k16.row.col.f32.bf16.bf16.f32 "
        "{%0,%1,%2,%3}, {%4,%5,%6,%7}, {%8,%9}, {%0,%1,%2,%3};"
        : "+f"(c[0]), "+f"(c[1]), "+f"(c[2]), "+f"(c[3])
        : "r"(a0), "r"(a1), "r"(a2), "r"(a3), "r"(b0), "r"(b1));
}

// ------------------- smem layout (M=256 tiles, single buffer) -------------------
#define A_HI 0
#define A_LO 32768
#define B_HI 65536
#define B_LO 69632
#define SM_N32 73728
#define C4B_HI 65536
#define C4B_LO 67584
#define SM_N16 69632

// conflict-free A-tile fill: 8 elements -> one STS.128 per tile
// swizzled column = jp ^ (tid&7): full permutation per 8-lane phase
__device__ __forceinline__ void sts_oct(char* buf, int tid, int jp, const uint32_t* v) {
    uint32_t off = sw128((uint32_t)(tid * 128 + jp * 16));
    uint4 h, l;
    h.x = __byte_perm(v[0], v[1], 0x5410); h.y = __byte_perm(v[2], v[3], 0x5410);
    h.z = __byte_perm(v[4], v[5], 0x5410); h.w = __byte_perm(v[6], v[7], 0x5410);
    l.x = __byte_perm(v[0], v[1], 0x7632); l.y = __byte_perm(v[2], v[3], 0x7632);
    l.z = __byte_perm(v[4], v[5], 0x7632); l.w = __byte_perm(v[6], v[7], 0x7632);
    *(uint4*)(buf + A_HI + off) = h;
    *(uint4*)(buf + A_LO + off) = l;
}

// consumer: 4 k-steps of one 64-wide K chunk, N=32, warp handles rows wid*32..+31
__device__ __forceinline__ void mma_chunk_n32(uint32_t sb, int wid, int lane, float* acc) {
#pragma unroll
    for (int ks = 0; ks < 4; ks++) {
        uint32_t a_hi[8], a_lo[8], b_hi[8], b_lo[8];
        uint32_t abyte = (uint32_t)((wid*32 + (lane & 15))*128 + (ks*16 + ((lane >> 4) << 3))*2);
        ldsm4(&a_hi[0], sb + A_HI + sw128(abyte));
        ldsm4(&a_hi[4], sb + A_HI + sw128(abyte) + 2048);
        ldsm4(&a_lo[0], sb + A_LO + sw128(abyte));
        ldsm4(&a_lo[4], sb + A_LO + sw128(abyte) + 2048);
        uint32_t bbyte = (uint32_t)(((((lane >> 4) << 3) + (lane & 7))*128) + (ks*16 + (lane & 8))*2);
        ldsm4(&b_hi[0], sb + B_HI + sw128(bbyte));
        ldsm4(&b_hi[4], sb + B_HI + sw128(bbyte) + 2048);
        ldsm4(&b_lo[0], sb + B_LO + sw128(bbyte));
        ldsm4(&b_lo[4], sb + B_LO + sw128(bbyte) + 2048);
#pragma unroll
        for (int mt = 0; mt < 2; mt++) {
#pragma unroll
            for (int nt = 0; nt < 4; nt++) {
                float* cc = acc + (mt*4 + nt)*4;
                const uint32_t* A  = a_hi + mt*4;
                const uint32_t* Al = a_lo + mt*4;
                uint32_t bh0 = b_hi[nt*2], bh1 = b_hi[nt*2+1];
                uint32_t bl0 = b_lo[nt*2], bl1 = b_lo[nt*2+1];
                mma_bf16(cc, A[0],A[1],A[2],A[3],   bh0, bh1);
                mma_bf16(cc, Al[0],Al[1],Al[2],Al[3], bh0, bh1);
                mma_bf16(cc, A[0],A[1],A[2],A[3],   bl0, bl1);
            }
        }
    }
}

// consumer: N=16 variant (conv4)
__device__ __forceinline__ void mma_chunk_n16(uint32_t sb, int wid, int lane, float* acc) {
#pragma unroll
    for (int ks = 0; ks < 4; ks++) {
        uint32_t a_hi[8], a_lo[8], b_hi[4], b_lo[4];
        uint32_t abyte = (uint32_t)((wid*32 + (lane & 15))*128 + (ks*16 + ((lane >> 4) << 3))*2);
        ldsm4(&a_hi[0], sb + A_HI + sw128(abyte));
        ldsm4(&a_hi[4], sb + A_HI + sw128(abyte) + 2048);
        ldsm4(&a_lo[0], sb + A_LO + sw128(abyte));
        ldsm4(&a_lo[4], sb + A_LO + sw128(abyte) + 2048);
        uint32_t bbyte = (uint32_t)(((((lane >> 4) << 3) + (lane & 7))*128) + (ks*16 + (lane & 8))*2);
        ldsm4(b_hi, sb + C4B_HI + sw128(bbyte));
        ldsm4(b_lo, sb + C4B_LO + sw128(bbyte));
#pragma unroll
        for (int mt = 0; mt < 2; mt++) {
#pragma unroll
            for (int nt = 0; nt < 2; nt++) {
                float* cc = acc + (mt*2 + nt)*4;
                const uint32_t* A  = a_hi + mt*4;
                const uint32_t* Al = a_lo + mt*4;
                uint32_t bh0 = b_hi[nt*2], bh1 = b_hi[nt*2+1];
                uint32_t bl0 = b_lo[nt*2], bl1 = b_lo[nt*2+1];
                mma_bf16(cc, A[0],A[1],A[2],A[3],   bh0, bh1);
                mma_bf16(cc, Al[0],Al[1],Al[2],Al[3], bh0, bh1);
                mma_bf16(cc, A[0],A[1],A[2],A[3],   bl0, bl1);
            }
        }
    }
}

// ------------------------- pre-pass kernels -------------------------
__global__ void split_x(const float* __restrict__ x) {
    int t = blockIdx.x * blockDim.x + threadIdx.x;
    if (t < BATCH*3*170*170) g_xHL[t] = packHL(x[t]);
}
__global__ void t_w1hl(const float* __restrict__ w) {
    int e = blockIdx.x * blockDim.x + threadIdx.x;
    if (e < 32*384) {
        int oc = e / 384, k = e - oc*384;
        g_w1HL[e] = (k < 363) ? packHL(w[oc*363 + k]) : 0u;
    }
}
__global__ void t_wrhl(const float* __restrict__ w) {
    int e = blockIdx.x * blockDim.x + threadIdx.x;
    if (e < 32*320) {
        int oc = e / 320, k = e - oc*320;
        int t9 = k >> 5, ic = k & 31;
        g_wrHL[e] = (t9 < 9) ? packHL(w[oc*288 + ic*9 + t9]) : 0u;
    }
}
__global__ void t_w4hl(const float* __restrict__ w) {
    int e = blockIdx.x * blockDim.x + threadIdx.x;
    if (e < 16*2048) g_w4HL[e] = packHL(w[e]);
}

// norm + PReLU + split, one pass
__global__ void act_kernel(const float* __restrict__ pa) {
    int t = blockIdx.x * blockDim.x + threadIdx.x;
    if (t >= BATCH*32*160*160) return;
    int xx = t % 160;
    int y  = (t / 160) % 160;
    int c  = (t / 25600) % 32;
    int region = (y / 40) * 4 + (xx / 40);
    float v = g_bufA[t];
    float r = fmaf(v, g_scale[region*32 + c], g_shift[region*32 + c]);
    float a = __ldg(pa);
    g_actHL[t] = packHL((r > 0.0f) ? r : a * r);
}

// ------------------------- conv1: implicit GEMM, M=256 pix, N=32, K=384 -------------------------
__global__ void __launch_bounds__(256) conv1_mma(const float* __restrict__ bias) {
    extern __shared__ char smem[];
    __shared__ __align__(16) int soffs[384];
    uint32_t sb = smem_u32(smem);
    int tid = threadIdx.x, wid = tid >> 5, lane = tid & 31;

    for (int k = tid; k < 384; k += 256) {
        if (k < 363) {
            int ic = k / 121;
            int r  = k - ic * 121;
            int ky = r / 11, kx = r - ky * 11;
            soffs[k] = ic * 28900 + ky * 170 + kx;
        } else soffs[k] = -1;
    }

    int p  = blockIdx.x * 256 + tid;
    int xo = p % 160, yo = (p / 160) % 160, b = p / 25600;
    const uint32_t* xin = g_xHL + b * 86700 + yo * 170 + xo;

    float acc[32];
#pragma unroll
    for (int i = 0; i < 32; i++) acc[i] = 0.f;
    __syncthreads();

    for (int c = 0; c < 6; c++) {
        int k0 = c * 64;
#pragma unroll 2
        for (int jp = 0; jp < 8; jp++) {
            int4 oa = *(const int4*)(soffs + k0 + 8*jp);
            int4 ob = *(const int4*)(soffs + k0 + 8*jp + 4);
            uint32_t v[8];
            v[0] = (oa.x >= 0) ? __ldg(xin + oa.x) : 0u;
            v[1] = (oa.y >= 0) ? __ldg(xin + oa.y) : 0u;
            v[2] = (oa.z >= 0) ? __ldg(xin + oa.z) : 0u;
            v[3] = (oa.w >= 0) ? __ldg(xin + oa.w) : 0u;
            v[4] = (ob.x >= 0) ? __ldg(xin + ob.x) : 0u;
            v[5] = (ob.y >= 0) ? __ldg(xin + ob.y) : 0u;
            v[6] = (ob.z >= 0) ? __ldg(xin + ob.z) : 0u;
            v[7] = (ob.w >= 0) ? __ldg(xin + ob.w) : 0u;
            sts_oct(smem, tid, jp, v);
        }
#pragma unroll
        for (int e = tid; e < 1024; e += 256) {
            int oc = e >> 5, i = e & 31;
            uint2 w2 = __ldg((const uint2*)(g_w1HL + oc*384 + k0 + 2*i));
            uint32_t off = sw128((uint32_t)(oc * 128 + i * 4));
            *(uint32_t*)(smem + B_HI + off) = __byte_perm(w2.x, w2.y, 0x5410);
            *(uint32_t*)(smem + B_LO + off) = __byte_perm(w2.x, w2.y, 0x7632);
        }
        __syncthreads();
        mma_chunk_n32(sb, wid, lane, acc);
        __syncthreads();
    }
    // two-phase epilogue
    float* stg = (float*)smem;
#pragma unroll
    for (int h = 0; h < 2; h++) {
        if ((wid >> 2) == h) {
#pragma unroll
            for (int mt = 0; mt < 2; mt++)
#pragma unroll
                for (int nt = 0; nt < 4; nt++)
#pragma unroll
                    for (int r = 0; r < 4; r++) {
                        int row = (wid & 3)*32 + mt*16 + (lane >> 2) + ((r >> 1) << 3);
                        int col = nt*8 + ((lane & 3) << 1) + (r & 1);
                        stg[row*33 + col] = acc[(mt*4 + nt)*4 + r];
                    }
        }
        __syncthreads();
        {
            int r  = tid & 127;
            int j0 = (tid >> 7) * 16;
            int pp = blockIdx.x * 256 + h * 128 + r;
            int xo2 = pp % 160, yo2 = (pp / 160) % 160, b2 = pp / 25600;
            float* op = g_bufA + (b2 * 32 * 160 + yo2) * 160 + xo2;
#pragma unroll
            for (int j = 0; j < 16; j++) {
                int jj = j0 + j;
                op[jj * 25600] = stg[r*33 + jj] + __ldg(bias + jj);
            }
        }
        __syncthreads();
    }
}

// ------------------------- per-(region,channel) stats -> scale/shift -------------------------
__global__ void stats_kernel(const float* __restrict__ gamma, const float* __restrict__ beta) {
    int rc = blockIdx.x;
    int region = rc >> 5;
    int c  = rc & 31;
    int ri = region >> 2, ci = region & 3;
    int tid = threadIdx.x;

    double s = 0.0, ss = 0.0;
    for (int i = tid; i < 64 * 1600; i += 256) {
        int b = i / 1600;
        int p = i - b * 1600;
        int y = ri * 40 + p / 40;
        int xx = ci * 40 + (p % 40);
        float v = g_bufA[((b * 32 + c) * 160 + y) * 160 + xx];
        s += (double)v; ss += (double)v * (double)v;
    }
    __shared__ double sh_s[256], sh_ss[256];
    sh_s[tid] = s; sh_ss[tid] = ss;
    __syncthreads();
    for (int off = 128; off > 0; off >>= 1) {
        if (tid < off) { sh_s[tid] += sh_s[tid + off]; sh_ss[tid] += sh_ss[tid + off]; }
        __syncthreads();
    }
    if (tid == 0) {
        double mean = sh_s[0] / 102400.0;
        double var  = sh_ss[0] / 102400.0 - mean * mean;
        float sc = __ldg(gamma + c) * rsqrtf((float)var + 1e-5f);
        g_scale[rc] = sc;
        g_shift[rc] = __ldg(beta + c) - (float)mean * sc;
    }
}

// ------------------------- rconv: implicit GEMM, M=256, N=32, K=320 -------------------------
__global__ void __launch_bounds__(256) rconv_mma(const float* __restrict__ bias) {
    extern __shared__ char smem[];
    uint32_t sb = smem_u32(smem);
    int tid = threadIdx.x, wid = tid >> 5, lane = tid & 31;

    int p  = blockIdx.x * 256 + tid;
    int xo = p % 160, yo = (p / 160) % 160, b = p / 25600;
    int lx = xo % 40, ly = yo % 40;
    const uint32_t* ain = g_actHL + b * 819200 + yo * 160 + xo;

    int ry = ((ly > 0) ? 1 : 0) | 2 | ((ly < 39) ? 4 : 0);
    int cx = ((lx > 0) ? 1 : 0) | 2 | ((lx < 39) ? 4 : 0);
    int mask = 0;
#pragma unroll
    for (int ty = 0; ty < 3; ty++)
#pragma unroll
        for (int tx = 0; tx < 3; tx++)
            if (((ry >> ty) & 1) && ((cx >> tx) & 1)) mask |= 1 << (ty*3 + tx);

    float acc[32];
#pragma unroll
    for (int i = 0; i < 32; i++) acc[i] = 0.f;

    for (int c = 0; c < 5; c++) {
        int k0 = c * 64;
        // two taps per 64-chunk: t0 = 2c (jp 0-3), t1 = 2c+1 (jp 4-7)
        int t0 = 2*c, t1 = 2*c + 1;
        bool ok0 = (t0 < 9) && ((mask >> t0) & 1);
        bool ok1 = (t1 < 9) && ((mask >> t1) & 1);
        int ty0 = t0 / 3, ty1 = t1 / 3;
        int dd0 = (ty0 - 1) * 160 + (t0 - ty0*3 - 1);
        int dd1 = (ty1 - 1) * 160 + (t1 - ty1*3 - 1);
#pragma unroll
        for (int jp = 0; jp < 8; jp++) {
            bool ok = (jp < 4) ? ok0 : ok1;
            int dd  = (jp < 4) ? dd0 : dd1;
            int ic  = (8*jp) & 31;
            uint32_t v[8];
            if (ok) {
                const uint32_t* q = ain + ic * 25600 + dd;
#pragma unroll
                for (int i = 0; i < 8; i++) v[i] = __ldg(q + i*25600);
            } else {
#pragma unroll
                for (int i = 0; i < 8; i++) v[i] = 0u;
            }
            sts_oct(smem, tid, jp, v);
        }
#pragma unroll
        for (int e = tid; e < 1024; e += 256) {
            int oc = e >> 5, i = e & 31;
            uint2 w2 = __ldg((const uint2*)(g_wrHL + oc*320 + k0 + 2*i));
            uint32_t off = sw128((uint32_t)(oc * 128 + i * 4));
            *(uint32_t*)(smem + B_HI + off) = __byte_perm(w2.x, w2.y, 0x5410);
            *(uint32_t*)(smem + B_LO + off) = __byte_perm(w2.x, w2.y, 0x7632);
        }
        __syncthreads();
        mma_chunk_n32(sb, wid, lane, acc);
        __syncthreads();
    }
    float* stg = (float*)smem;
#pragma unroll
    for (int h = 0; h < 2; h++) {
        if ((wid >> 2) == h) {
#pragma unroll
            for (int mt = 0; mt < 2; mt++)
#pragma unroll
                for (int nt = 0; nt < 4; nt++)
#pragma unroll
                    for (int r = 0; r < 4; r++) {
                        int row = (wid & 3)*32 + mt*16 + (lane >> 2) + ((r >> 1) << 3);
                        int col = nt*8 + ((lane & 3) << 1) + (r & 1);
                        stg[row*33 + col] = acc[(mt*4 + nt)*4 + r];
                    }
        }
        __syncthreads();
        {
            int r  = tid & 127;
            int j0 = (tid >> 7) * 16;
            int pp = blockIdx.x * 256 + h * 128 + r;
            int xo2 = pp % 160, yo2 = (pp / 160) % 160, b2 = pp / 25600;
            float* op = g_bufB + (b2 * 32 * 160 + yo2) * 160 + xo2;
#pragma unroll
            for (int j = 0; j < 16; j++) {
                int jj = j0 + j;
                op[jj * 25600] = stg[r*33 + jj] + __ldg(bias + jj);
            }
        }
        __syncthreads();
    }
}

// ------------------------- 2x2 maxpool, 160->80, fused split -------------------------
__global__ void pool_kernel() {
    int t = blockIdx.x * blockDim.x + threadIdx.x;
    if (t >= BATCH * 32 * 80 * 80) return;
    int xx = t % 80;
    int y  = (t / 80) % 80;
    int bc = t / 6400;
    const float* p = g_bufB + (bc * 160 + 2 * y) * 160 + 2 * xx;
    g_poolHL[t] = packHL(fmaxf(fmaxf(p[0], p[1]), fmaxf(p[160], p[161])));
}

// ------------------------- conv4: implicit GEMM, M=256, N=16, K=2048 -------------------------
#define CONV4_M (BATCH * 73 * 73)
__global__ void __launch_bounds__(256) conv4_mma(const float* __restrict__ bias) {
    extern __shared__ char smem[];
    uint32_t sb = smem_u32(smem);
    int tid = threadIdx.x, wid = tid >> 5, lane = tid & 31;

    int p  = blockIdx.x * 256 + tid;
    bool pv = p < CONV4_M;
    int pp = pv ? p : 0;
    int xo = pp % 73, yo = (pp / 73) % 73, b = pp / 5329;
    const uint32_t* pin = g_poolHL + b * 204800 + yo * 80 + xo;

    float acc[16];
#pragma unroll
    for (int i = 0; i < 16; i++) acc[i] = 0.f;

    for (int c = 0; c < 32; c++) {
        int k0 = c * 64;
#pragma unroll 2
        for (int jp = 0; jp < 8; jp++) {
            int k  = k0 + 8*jp;            // kx = 0..7 within one input row
            const uint32_t* q = pin + (k >> 6) * 6400 + ((k & 63) >> 3) * 80;
            uint32_t v[8];
            if (pv) {
#pragma unroll
                for (int i = 0; i < 8; i++) v[i] = __ldg(q + i);
            } else {
#pragma unroll
                for (int i = 0; i < 8; i++) v[i] = 0u;
            }
            sts_oct(smem, tid, jp, v);
        }
#pragma unroll
        for (int e = tid; e < 512; e += 256) {
            int oc = e >> 5, i = e & 31;
            uint2 w2 = __ldg((const uint2*)(g_w4HL + oc*2048 + k0 + 2*i));
            uint32_t off = sw128((uint32_t)(oc * 128 + i * 4));
            *(uint32_t*)(smem + C4B_HI + off) = __byte_perm(w2.x, w2.y, 0x5410);
            *(uint32_t*)(smem + C4B_LO + off) = __byte_perm(w2.x, w2.y, 0x7632);
        }
        __syncthreads();
        mma_chunk_n16(sb, wid, lane, acc);
        __syncthreads();
    }
    float* stg = (float*)smem;
#pragma unroll
    for (int h = 0; h < 2; h++) {
        if ((wid >> 2) == h) {
#pragma unroll
            for (int mt = 0; mt < 2; mt++)
#pragma unroll
                for (int nt = 0; nt < 2; nt++)
#pragma unroll
                    for (int r = 0; r < 4; r++) {
                        int row = (wid & 3)*32 + mt*16 + (lane >> 2) + ((r >> 1) << 3);
                        int col = nt*8 + ((lane & 3) << 1) + (r & 1);
                        stg[row*17 + col] = acc[(mt*2 + nt)*4 + r];
                    }
        }
        __syncthreads();
        {
            int r  = tid & 127;
            int j0 = (tid >> 7) * 8;
            int pq = blockIdx.x * 256 + h * 128 + r;
            if (pq < CONV4_M) {
                int xo2 = pq % 73, yo2 = (pq / 73) % 73, b2 = pq / 5329;
                float* op = g_c4 + (b2 * 16 * 73 + yo2) * 73 + xo2;
#pragma unroll
                for (int j = 0; j < 8; j++) {
                    int jj = j0 + j;
                    op[jj * 5329] = stg[r*17 + jj] + __ldg(bias + jj);
                }
            }
        }
        __syncthreads();
    }
}

// ------------------------- weight transpose for remaining direct convs -------------------------
#define DEFINE_TRANS(NAME, OC, R, DST)                                        \
__global__ void NAME(const float* __restrict__ w) {                           \
    int e = blockIdx.x * blockDim.x + threadIdx.x;                            \
    if (e < (OC)*(R)) {                                                       \
        int oc = e / (R);                                                     \
        int r  = e - oc * (R);                                                \
        DST[r*(OC) + oc] = w[e];                                              \
    }                                                                         \
}
DEFINE_TRANS(t_w5,  16, 1024, g_wT5)
DEFINE_TRANS(t_w6,  16,  576, g_wT6)
DEFINE_TRANS(t_w7,  16,  400, g_wT7)
DEFINE_TRANS(t_w8,  16,  144, g_wT8)
DEFINE_TRANS(t_wfc, 512, 1024, g_wTfc)

// ------------------------- generic OC=16 direct conv, 2 pixels/thread -------------------------
#define DEFINE_CONV16(NAME, IC, K, S, IH, IW, OH, OW, INBUF, WTBUF, OUTBUF)          \
__global__ void __launch_bounds__(128) NAME(const float* __restrict__ bias) {        \
    const int XP  = ((OW) + 1) / 2;                                                  \
    const int OFF = (OW) - XP;                                                       \
    int t = blockIdx.x * 128 + threadIdx.x;                                          \
    if (t >= BATCH * (OH) * XP) return;                                              \
    int xo = t % XP;                                                                 \
    int yo = (t / XP) % (OH);                                                        \
    int b  = t / (XP * (OH));                                                        \
    float a0[16], a1[16];                                                            \
    _Pragma("unroll")                                                                \
    for (int j = 0; j < 16; j++) { float bv = __ldg(bias + j); a0[j] = bv; a1[j] = bv; } \
    for (int ic = 0; ic < (IC); ic++) {                                              \
        const float* inp = INBUF + ((b*(IC) + ic)*(IH) + yo*(S))*(IW) + xo*(S);      \
        _Pragma("unroll 1")                                                          \
        for (int ky = 0; ky < (K); ky++) {                                           \
            const float* row = inp + ky*(IW);                                        \
            const float4* wrow = (const float4*)(WTBUF + (ic*(K)*(K) + ky*(K))*16);  \
            _Pragma("unroll")                                                        \
            for (int kx = 0; kx < (K); kx++) {                                       \
                float v0 = __ldg(row + kx);                                          \
                float v1 = __ldg(row + OFF*(S) + kx);                                \
                _Pragma("unroll")                                                    \
                for (int j = 0; j < 4; j++) {                                        \
                    float4 w4 = __ldg(wrow + kx*4 + j);                              \
                    a0[4*j+0] = fmaf(v0, w4.x, a0[4*j+0]); a1[4*j+0] = fmaf(v1, w4.x, a1[4*j+0]); \
                    a0[4*j+1] = fmaf(v0, w4.y, a0[4*j+1]); a1[4*j+1] = fmaf(v1, w4.y, a1[4*j+1]); \
                    a0[4*j+2] = fmaf(v0, w4.z, a0[4*j+2]); a1[4*j+2] = fmaf(v1, w4.z, a1[4*j+2]); \
                    a0[4*j+3] = fmaf(v0, w4.w, a0[4*j+3]); a1[4*j+3] = fmaf(v1, w4.w, a1[4*j+3]); \
                }                                                                    \
            }                                                                        \
        }                                                                            \
    }                                                                                \
    float* op = OUTBUF + (b*16*(OH) + yo)*(OW) + xo;                                 \
    _Pragma("unroll")                                                                \
    for (int j = 0; j < 16; j++) {                                                   \
        op[j*(OH)*(OW)]       = a0[j];                                               \
        op[j*(OH)*(OW) + OFF] = a1[j];                                               \
    }                                                                                \
}

DEFINE_CONV16(conv5_kernel, 16, 8, 2, 73, 73, 33, 33, g_c4, g_wT5, g_c5)
DEFINE_CONV16(conv6_kernel, 16, 6, 1, 33, 33, 28, 28, g_c5, g_wT6, g_c6)
DEFINE_CONV16(conv7_kernel, 16, 5, 1, 28, 28, 24, 24, g_c6, g_wT7, g_c7)
DEFINE_CONV16(conv8_kernel, 16, 3, 3, 24, 24,  8,  8, g_c7, g_wT8, g_c8)

// ------------------------- FC -------------------------
__global__ void fc_kernel(const float* __restrict__ bias, float* __restrict__ out) {
    __shared__ float sm[1024];
    int b = blockIdx.x;
    int o = threadIdx.x;
    sm[o]       = g_c8[b * 1024 + o];
    sm[o + 512] = g_c8[b * 1024 + o + 512];
    __syncthreads();
    float acc = __ldg(bias + o);
#pragma unroll 4
    for (int k = 0; k < 1024; k++)
        acc = fmaf(sm[k], g_wTfc[k * 512 + o], acc);
    out[b * 512 + o] = acc;
}

// ------------------------- launch -------------------------
static inline int gridFor(long n, int bs) { return (int)((n + bs - 1) / bs); }

extern "C" void kernel_launch(void* const* d_in, const int* in_sizes, int n_in,
                              void* d_out, int out_size) {
    const float* x        = (const float*)d_in[0];
    const float* conv1_w  = (const float*)d_in[1];
    const float* conv1_b  = (const float*)d_in[2];
    const float* bn_gamma = (const float*)d_in[3];
    const float* bn_beta  = (const float*)d_in[4];
    const float* prelu_a  = (const float*)d_in[5];
    const float* rconv_w  = (const float*)d_in[6];
    const float* rconv_b  = (const float*)d_in[7];
    const float* conv4_w  = (const float*)d_in[8];
    const float* conv4_b  = (const float*)d_in[9];
    const float* conv5_b  = (const float*)d_in[11];
    const float* conv6_b  = (const float*)d_in[13];
    const float* conv7_b  = (const float*)d_in[15];
    const float* conv8_b  = (const float*)d_in[17];
    const float* fc_b     = (const float*)d_in[19];
    float* out = (float*)d_out;

    cudaFuncSetAttribute(conv1_mma, cudaFuncAttributeMaxDynamicSharedMemorySize, SM_N32);
    cudaFuncSetAttribute(rconv_mma, cudaFuncAttributeMaxDynamicSharedMemorySize, SM_N32);
    cudaFuncSetAttribute(conv4_mma, cudaFuncAttributeMaxDynamicSharedMemorySize, SM_N16);

    // launches ordered so conv1_mma is the 4th launch (ncu captures launch #4)
    split_x<<<gridFor((long)BATCH*3*170*170, 256), 256>>>(x);
    t_w1hl<<<gridFor(32*384, 256), 256>>>(conv1_w);
    t_wrhl<<<gridFor(32*320, 256), 256>>>(rconv_w);
    conv1_mma<<<6400, 256, SM_N32>>>(conv1_b);

    t_w4hl<<<gridFor(16*2048, 256), 256>>>(conv4_w);
    t_w5 <<<gridFor(16*1024, 256), 256>>>((const float*)d_in[10]);
    t_w6 <<<gridFor(16*576,  256), 256>>>((const float*)d_in[12]);
    t_w7 <<<gridFor(16*400,  256), 256>>>((const float*)d_in[14]);
    t_w8 <<<gridFor(16*144,  256), 256>>>((const float*)d_in[16]);
    t_wfc<<<gridFor(512*1024,256), 256>>>((const float*)d_in[18]);

    stats_kernel<<<512, 256>>>(bn_gamma, bn_beta);
    act_kernel<<<gridFor((long)BATCH*32*160*160, 256), 256>>>(prelu_a);
    rconv_mma<<<6400, 256, SM_N32>>>(rconv_b);
    pool_kernel<<<gridFor((long)BATCH*32*80*80, 256), 256>>>();

    conv4_mma<<<gridFor(CONV4_M, 256), 256, SM_N16>>>(conv4_b);
    conv5_kernel<<<gridFor((long)BATCH*33*17, 128), 128>>>(conv5_b);
    conv6_kernel<<<gridFor((long)BATCH*28*14, 128), 128>>>(conv6_b);
    conv7_kernel<<<gridFor((long)BATCH*24*12, 128), 128>>>(conv7_b);
    conv8_kernel<<<gridFor((long)BATCH*8*4,   128), 128>>>(conv8_b);

    fc_kernel<<<BATCH, 512>>>(fc_b, out);
}

// round 8
// speedup vs baseline: 1.9168x; 1.1346x over previous
#include <cuda_runtime.h>
#include <cuda_bf16.h>
#include <cstdint>

#define BATCH 64

// ------------------------- scratch (no allocs allowed) -------------------------
__device__ float    g_bufA[BATCH*32*160*160];   // conv1 out (fp32, for stats)
__device__ float    g_bufB[BATCH*32*160*160];   // rconv out (fp32, for pool)
__device__ uint32_t g_xHL[BATCH*3*170*170];     // input, packed hi/lo bf16
__device__ uint32_t g_actHL[BATCH*32*160*160];  // norm+PReLU(conv1 out), packed
__device__ uint32_t g_poolHL[BATCH*32*80*80];   // pooled, packed
__device__ float g_c4[BATCH*16*73*73];
__device__ float g_c5[BATCH*16*33*33];
__device__ float g_c6[BATCH*16*28*28];
__device__ float g_c7[BATCH*16*24*24];
__device__ float g_c8[BATCH*16*8*8];

__device__ uint32_t g_w1HL[32*384];    // conv1 w, K padded 363->384
__device__ uint32_t g_wrHL[32*320];    // rconv w, reordered k=t*32+ic, padded 288->320
__device__ uint32_t g_w4HL[16*2048];   // conv4 w

__device__ float g_wT5[1024*16];
__device__ float g_wT6[576*16];
__device__ float g_wT7[400*16];
__device__ float g_wT8[144*16];
__device__ float g_wTfc[1024*512];

__device__ float g_scale[512];   // [region(16)][channel(32)]
__device__ float g_shift[512];

// ------------------------- helpers -------------------------
__device__ __forceinline__ uint32_t smem_u32(const void* p) {
    uint32_t a;
    asm("{ .reg .u64 t; cvta.to.shared.u64 t, %1; cvt.u32.u64 %0, t; }" : "=r"(a) : "l"(p));
    return a;
}
__device__ __forceinline__ uint32_t sw128(uint32_t o) { return o ^ ((o >> 3) & 0x70); }

__device__ __forceinline__ uint32_t packHL(float v) {
    __nv_bfloat16 h = __float2bfloat16(v);
    float r = v - __bfloat162float(h);
    __nv_bfloat16 l = __float2bfloat16(r);
    uint16_t hb = *reinterpret_cast<uint16_t*>(&h);
    uint16_t lb = *reinterpret_cast<uint16_t*>(&l);
    return (uint32_t)hb | ((uint32_t)lb << 16);
}

__device__ __forceinline__ void ldsm4(uint32_t* r, uint32_t addr) {
    asm volatile("ldmatrix.sync.aligned.m8n8.x4.shared.b16 {%0,%1,%2,%3}, [%4];"
                 : "=r"(r[0]), "=r"(r[1]), "=r"(r[2]), "=r"(r[3]) : "r"(addr));
}

__device__ __forceinline__ void mma_bf16(float* c,
        uint32_t a0, uint32_t a1, uint32_t a2, uint32_t a3,
        uint32_t b0, uint32_t b1) {
    asm volatile(
        "mma.sync.aligned.m16n8k16.row.col.f32.bf16.bf16.f32 "
        "{%0,%1,%2,%3}, {%4,%5,%6,%7}, {%8,%9}, {%0,%1,%2,%3};"
        : "+f"(c[0]), "+f"(c[1]), "+f"(c[2]), "+f"(c[3])
        : "r"(a0), "r"(a1), "r"(a2), "r"(a3), "r"(b0), "r"(b1));
}

// A fragment build: 8 HL words -> 4 hi regs + 4 lo regs, then 3-term MMAs vs 4 B-col pairs
#define MMA_TERMS_N(NT, ACCM)                                                       \
    do {                                                                            \
        uint32_t ah0=__byte_perm(w00,w01,0x5410), ah1=__byte_perm(w10,w11,0x5410);  \
        uint32_t ah2=__byte_perm(w02,w03,0x5410), ah3=__byte_perm(w12,w13,0x5410);  \
        uint32_t al0=__byte_perm(w00,w01,0x7632), al1=__byte_perm(w10,w11,0x7632);  \
        uint32_t al2=__byte_perm(w02,w03,0x7632), al3=__byte_perm(w12,w13,0x7632);  \
        _Pragma("unroll")                                                           \
        for (int nt = 0; nt < (NT); nt++) {                                         \
            float* cc2 = (ACCM) + nt*4;                                             \
            mma_bf16(cc2, ah0,ah1,ah2,ah3, b_hi[nt*2], b_hi[nt*2+1]);               \
            mma_bf16(cc2, al0,al1,al2,al3, b_hi[nt*2], b_hi[nt*2+1]);               \
            mma_bf16(cc2, ah0,ah1,ah2,ah3, b_lo[nt*2], b_lo[nt*2+1]);               \
        }                                                                           \
    } while (0)

// ------------------------- pre-pass kernels -------------------------
__global__ void split_x(const float* __restrict__ x) {
    int t = blockIdx.x * blockDim.x + threadIdx.x;
    if (t < BATCH*3*170*170) g_xHL[t] = packHL(x[t]);
}
__global__ void t_w1hl(const float* __restrict__ w) {
    int e = blockIdx.x * blockDim.x + threadIdx.x;
    if (e < 32*384) {
        int oc = e / 384, k = e - oc*384;
        g_w1HL[e] = (k < 363) ? packHL(w[oc*363 + k]) : 0u;
    }
}
__global__ void t_wrhl(const float* __restrict__ w) {
    int e = blockIdx.x * blockDim.x + threadIdx.x;
    if (e < 32*320) {
        int oc = e / 320, k = e - oc*320;
        int t9 = k >> 5, ic = k & 31;
        g_wrHL[e] = (t9 < 9) ? packHL(w[oc*288 + ic*9 + t9]) : 0u;
    }
}
__global__ void t_w4hl(const float* __restrict__ w) {
    int e = blockIdx.x * blockDim.x + threadIdx.x;
    if (e < 16*2048) g_w4HL[e] = packHL(w[e]);
}

// norm + PReLU + split, one pass
__global__ void act_kernel(const float* __restrict__ pa) {
    int t = blockIdx.x * blockDim.x + threadIdx.x;
    if (t >= BATCH*32*160*160) return;
    int xx = t % 160;
    int y  = (t / 160) % 160;
    int c  = (t / 25600) % 32;
    int region = (y / 40) * 4 + (xx / 40);
    float v = g_bufA[t];
    float r = fmaf(v, g_scale[region*32 + c], g_shift[region*32 + c]);
    float a = __ldg(pa);
    g_actHL[t] = packHL((r > 0.0f) ? r : a * r);
}

// ------------------------- conv1: direct-fragment implicit GEMM, M=256, N=32, K=384 -------------------------
// SMEM: B_HI 6*4096 @0, B_LO 6*4096 @24576, total 49152; epilogue staging reuses @0.
#define C1_SM 49152
__global__ void __launch_bounds__(256) conv1_mma(const float* __restrict__ bias) {
    extern __shared__ char smem[];
    __shared__ __align__(16) int soffs[384];
    uint32_t sb = smem_u32(smem);
    int tid = threadIdx.x, wid = tid >> 5, lane = tid & 31;

    for (int k = tid; k < 384; k += 256) {
        if (k < 363) {
            int ic = k / 121;
            int r  = k - ic * 121;
            int ky = r / 11, kx = r - ky * 11;
            soffs[k] = ic * 28900 + ky * 170 + kx;
        } else soffs[k] = -1;
    }

    // stage full B once
#pragma unroll
    for (int e = tid; e < 6144; e += 256) {
        int chunk = e >> 10, idx = e & 1023;
        int oc = idx >> 5, i = idx & 31;
        uint2 w2 = __ldg((const uint2*)(g_w1HL + oc*384 + chunk*64 + 2*i));
        uint32_t off = chunk*4096 + sw128((uint32_t)(oc*128 + i*4));
        *(uint32_t*)(smem + off)         = __byte_perm(w2.x, w2.y, 0x5410);
        *(uint32_t*)(smem + 24576 + off) = __byte_perm(w2.x, w2.y, 0x7632);
    }

    // 4 pixel pointers: h = mt*2 + half; pixel = blk*256 + wid*32 + mt*16 + half*8 + lane>>2
    const uint32_t* xp[4];
#pragma unroll
    for (int h = 0; h < 4; h++) {
        int pp = blockIdx.x*256 + wid*32 + (h>>1)*16 + (h&1)*8 + (lane>>2);
        int xo = pp % 160, yo = (pp/160) % 160, b = pp / 25600;
        xp[h] = g_xHL + b*86700 + yo*170 + xo;
    }

    float acc[32];
#pragma unroll
    for (int i = 0; i < 32; i++) acc[i] = 0.f;
    __syncthreads();

    for (int c = 0; c < 6; c++) {
        uint32_t bHiBase = sb + c*4096;
        uint32_t bLoBase = sb + 24576 + c*4096;
#pragma unroll
        for (int ks = 0; ks < 4; ks++) {
            int kA = c*64 + ks*16 + ((lane & 3) << 1);
            int2 oA = *(const int2*)(soffs + kA);
            int2 oB = *(const int2*)(soffs + kA + 8);
            uint32_t b_hi[8], b_lo[8];
            uint32_t bbyte = (uint32_t)(((((lane >> 4) << 3) + (lane & 7))*128) + (ks*16 + (lane & 8))*2);
            ldsm4(&b_hi[0], bHiBase + sw128(bbyte));
            ldsm4(&b_hi[4], bHiBase + sw128(bbyte) + 2048);
            ldsm4(&b_lo[0], bLoBase + sw128(bbyte));
            ldsm4(&b_lo[4], bLoBase + sw128(bbyte) + 2048);
#pragma unroll
            for (int mt = 0; mt < 2; mt++) {
                const uint32_t* q0 = xp[mt*2 + 0];
                const uint32_t* q1 = xp[mt*2 + 1];
                uint32_t w00 = (oA.x >= 0) ? __ldg(q0 + oA.x) : 0u;
                uint32_t w01 = (oA.y >= 0) ? __ldg(q0 + oA.y) : 0u;
                uint32_t w10 = (oA.x >= 0) ? __ldg(q1 + oA.x) : 0u;
                uint32_t w11 = (oA.y >= 0) ? __ldg(q1 + oA.y) : 0u;
                uint32_t w02 = (oB.x >= 0) ? __ldg(q0 + oB.x) : 0u;
                uint32_t w03 = (oB.y >= 0) ? __ldg(q0 + oB.y) : 0u;
                uint32_t w12 = (oB.x >= 0) ? __ldg(q1 + oB.x) : 0u;
                uint32_t w13 = (oB.y >= 0) ? __ldg(q1 + oB.y) : 0u;
                MMA_TERMS_N(4, acc + mt*16);
            }
        }
    }
    // epilogue (reuses smem)
    __syncthreads();
    float* stg = (float*)smem;
#pragma unroll
    for (int h = 0; h < 2; h++) {
        if ((wid >> 2) == h) {
#pragma unroll
            for (int mt = 0; mt < 2; mt++)
#pragma unroll
                for (int nt = 0; nt < 4; nt++)
#pragma unroll
                    for (int r = 0; r < 4; r++) {
                        int row = (wid & 3)*32 + mt*16 + (lane >> 2) + ((r >> 1) << 3);
                        int col = nt*8 + ((lane & 3) << 1) + (r & 1);
                        stg[row*33 + col] = acc[(mt*4 + nt)*4 + r];
                    }
        }
        __syncthreads();
        {
            int r  = tid & 127;
            int j0 = (tid >> 7) * 16;
            int pp = blockIdx.x * 256 + h * 128 + r;
            int xo2 = pp % 160, yo2 = (pp / 160) % 160, b2 = pp / 25600;
            float* op = g_bufA + (b2 * 32 * 160 + yo2) * 160 + xo2;
#pragma unroll
            for (int j = 0; j < 16; j++) {
                int jj = j0 + j;
                op[jj * 25600] = stg[r*33 + jj] + __ldg(bias + jj);
            }
        }
        __syncthreads();
    }
}

// ------------------------- per-(region,channel) stats -> scale/shift -------------------------
__global__ void stats_kernel(const float* __restrict__ gamma, const float* __restrict__ beta) {
    int rc = blockIdx.x;
    int region = rc >> 5;
    int c  = rc & 31;
    int ri = region >> 2, ci = region & 3;
    int tid = threadIdx.x;

    double s = 0.0, ss = 0.0;
    for (int i = tid; i < 64 * 1600; i += 256) {
        int b = i / 1600;
        int p = i - b * 1600;
        int y = ri * 40 + p / 40;
        int xx = ci * 40 + (p % 40);
        float v = g_bufA[((b * 32 + c) * 160 + y) * 160 + xx];
        s += (double)v; ss += (double)v * (double)v;
    }
    __shared__ double sh_s[256], sh_ss[256];
    sh_s[tid] = s; sh_ss[tid] = ss;
    __syncthreads();
    for (int off = 128; off > 0; off >>= 1) {
        if (tid < off) { sh_s[tid] += sh_s[tid + off]; sh_ss[tid] += sh_ss[tid + off]; }
        __syncthreads();
    }
    if (tid == 0) {
        double mean = sh_s[0] / 102400.0;
        double var  = sh_ss[0] / 102400.0 - mean * mean;
        float sc = __ldg(gamma + c) * rsqrtf((float)var + 1e-5f);
        g_scale[rc] = sc;
        g_shift[rc] = __ldg(beta + c) - (float)mean * sc;
    }
}

// ------------------------- rconv: direct-fragment implicit GEMM, M=256, N=32, K=320 -------------------------
// SMEM: B_HI 5*4096 @0, B_LO @20480, total 40960; staging reuses @0.
#define RC_SM 40960
__global__ void __launch_bounds__(256) rconv_mma(const float* __restrict__ bias) {
    extern __shared__ char smem[];
    uint32_t sb = smem_u32(smem);
    int tid = threadIdx.x, wid = tid >> 5, lane = tid & 31;

    // stage full B once
#pragma unroll
    for (int e = tid; e < 5120; e += 256) {
        int chunk = e >> 10, idx = e & 1023;
        int oc = idx >> 5, i = idx & 31;
        uint2 w2 = __ldg((const uint2*)(g_wrHL + oc*320 + chunk*64 + 2*i));
        uint32_t off = chunk*4096 + sw128((uint32_t)(oc*128 + i*4));
        *(uint32_t*)(smem + off)         = __byte_perm(w2.x, w2.y, 0x5410);
        *(uint32_t*)(smem + 20480 + off) = __byte_perm(w2.x, w2.y, 0x7632);
    }

    const uint32_t* xp[4];
    int msk[4];
#pragma unroll
    for (int h = 0; h < 4; h++) {
        int pp = blockIdx.x*256 + wid*32 + (h>>1)*16 + (h&1)*8 + (lane>>2);
        int xo = pp % 160, yo = (pp/160) % 160, b = pp / 25600;
        xp[h] = g_actHL + b*819200 + yo*160 + xo;
        int lx = xo % 40, ly = yo % 40;
        int ry = ((ly > 0) ? 1 : 0) | 2 | ((ly < 39) ? 4 : 0);
        int cx = ((lx > 0) ? 1 : 0) | 2 | ((lx < 39) ? 4 : 0);
        int m = 0;
#pragma unroll
        for (int ty = 0; ty < 3; ty++)
#pragma unroll
            for (int tx = 0; tx < 3; tx++)
                if (((ry >> ty) & 1) && ((cx >> tx) & 1)) m |= 1 << (ty*3 + tx);
        msk[h] = m;
    }

    float acc[32];
#pragma unroll
    for (int i = 0; i < 32; i++) acc[i] = 0.f;
    __syncthreads();

    for (int c = 0; c < 5; c++) {
        uint32_t bHiBase = sb + c*4096;
        uint32_t bLoBase = sb + 20480 + c*4096;
        int t0 = 2*c, t1 = 2*c + 1;
        int ty0 = t0 / 3, ty1 = t1 / 3;
        int dd0 = (ty0 - 1)*160 + (t0 - 3*ty0 - 1);
        int dd1 = (ty1 - 1)*160 + (t1 - 3*ty1 - 1);
#pragma unroll
        for (int ks = 0; ks < 4; ks++) {
            bool useT1 = (ks >= 2);
            int t   = useT1 ? t1 : t0;
            int dd  = useT1 ? dd1 : dd0;
            bool tv = (t < 9);
            int icb = (ks & 1)*16 + ((lane & 3) << 1);
            int co0 = icb*25600 + dd;          // kA
            int co1 = co0 + 25600;             // kA+1
            int co2 = co0 + 204800;            // kA+8
            int co3 = co2 + 25600;             // kA+9
            uint32_t b_hi[8], b_lo[8];
            uint32_t bbyte = (uint32_t)(((((lane >> 4) << 3) + (lane & 7))*128) + (ks*16 + (lane & 8))*2);
            ldsm4(&b_hi[0], bHiBase + sw128(bbyte));
            ldsm4(&b_hi[4], bHiBase + sw128(bbyte) + 2048);
            ldsm4(&b_lo[0], bLoBase + sw128(bbyte));
            ldsm4(&b_lo[4], bLoBase + sw128(bbyte) + 2048);
#pragma unroll
            for (int mt = 0; mt < 2; mt++) {
                const uint32_t* q0 = xp[mt*2 + 0];
                const uint32_t* q1 = xp[mt*2 + 1];
                bool ok0 = tv && ((msk[mt*2 + 0] >> t) & 1);
                bool ok1 = tv && ((msk[mt*2 + 1] >> t) & 1);
                uint32_t w00 = ok0 ? __ldg(q0 + co0) : 0u;
                uint32_t w01 = ok0 ? __ldg(q0 + co1) : 0u;
                uint32_t w02 = ok0 ? __ldg(q0 + co2) : 0u;
                uint32_t w03 = ok0 ? __ldg(q0 + co3) : 0u;
                uint32_t w10 = ok1 ? __ldg(q1 + co0) : 0u;
                uint32_t w11 = ok1 ? __ldg(q1 + co1) : 0u;
                uint32_t w12 = ok1 ? __ldg(q1 + co2) : 0u;
                uint32_t w13 = ok1 ? __ldg(q1 + co3) : 0u;
                MMA_TERMS_N(4, acc + mt*16);
            }
        }
    }
    __syncthreads();
    float* stg = (float*)smem;
#pragma unroll
    for (int h = 0; h < 2; h++) {
        if ((wid >> 2) == h) {
#pragma unroll
            for (int mt = 0; mt < 2; mt++)
#pragma unroll
                for (int nt = 0; nt < 4; nt++)
#pragma unroll
                    for (int r = 0; r < 4; r++) {
                        int row = (wid & 3)*32 + mt*16 + (lane >> 2) + ((r >> 1) << 3);
                        int col = nt*8 + ((lane & 3) << 1) + (r & 1);
                        stg[row*33 + col] = acc[(mt*4 + nt)*4 + r];
                    }
        }
        __syncthreads();
        {
            int r  = tid & 127;
            int j0 = (tid >> 7) * 16;
            int pp = blockIdx.x * 256 + h * 128 + r;
            int xo2 = pp % 160, yo2 = (pp / 160) % 160, b2 = pp / 25600;
            float* op = g_bufB + (b2 * 32 * 160 + yo2) * 160 + xo2;
#pragma unroll
            for (int j = 0; j < 16; j++) {
                int jj = j0 + j;
                op[jj * 25600] = stg[r*33 + jj] + __ldg(bias + jj);
            }
        }
        __syncthreads();
    }
}

// ------------------------- 2x2 maxpool, 160->80, fused split -------------------------
__global__ void pool_kernel() {
    int t = blockIdx.x * blockDim.x + threadIdx.x;
    if (t >= BATCH * 32 * 80 * 80) return;
    int xx = t % 80;
    int y  = (t / 80) % 80;
    int bc = t / 6400;
    const float* p = g_bufB + (bc * 160 + 2 * y) * 160 + 2 * xx;
    g_poolHL[t] = packHL(fmaxf(fmaxf(p[0], p[1]), fmaxf(p[160], p[161])));
}

// ------------------------- conv4: direct-fragment implicit GEMM, M=256, N=16, K=2048 -------------------------
// SMEM: quarter B (8 chunks): HI 16KB @0, LO 16KB @16384; staging reuses @0.
#define CONV4_M (BATCH * 73 * 73)
#define C4_SM 32768
__global__ void __launch_bounds__(256) conv4_mma(const float* __restrict__ bias) {
    extern __shared__ char smem[];
    uint32_t sb = smem_u32(smem);
    int tid = threadIdx.x, wid = tid >> 5, lane = tid & 31;

    const uint32_t* xp[4];
    bool pvh[4];
#pragma unroll
    for (int h = 0; h < 4; h++) {
        int pp = blockIdx.x*256 + wid*32 + (h>>1)*16 + (h&1)*8 + (lane>>2);
        pvh[h] = pp < CONV4_M;
        int pq = pvh[h] ? pp : 0;
        int xo = pq % 73, yo = (pq/73) % 73, b = pq / 5329;
        xp[h] = g_poolHL + b*204800 + yo*80 + xo;
    }

    float acc[16];
#pragma unroll
    for (int i = 0; i < 16; i++) acc[i] = 0.f;

    for (int qt = 0; qt < 4; qt++) {
        if (qt) __syncthreads();
        // stage quarter B (8 chunks of 64k, 16 oc)
#pragma unroll
        for (int e = tid; e < 4096; e += 256) {
            int chunk = e >> 9, idx = e & 511;
            int oc = idx >> 5, i = idx & 31;
            uint2 w2 = __ldg((const uint2*)(g_w4HL + oc*2048 + qt*512 + chunk*64 + 2*i));
            uint32_t off = chunk*2048 + sw128((uint32_t)(oc*128 + i*4));
            *(uint32_t*)(smem + off)         = __byte_perm(w2.x, w2.y, 0x5410);
            *(uint32_t*)(smem + 16384 + off) = __byte_perm(w2.x, w2.y, 0x7632);
        }
        __syncthreads();
#pragma unroll 1
        for (int cc = 0; cc < 8; cc++) {
            int c = qt*8 + cc;
            uint32_t bHiBase = sb + cc*2048;
            uint32_t bLoBase = sb + 16384 + cc*2048;
#pragma unroll
            for (int ks = 0; ks < 4; ks++) {
                int k  = c*64 + ks*16 + ((lane & 3) << 1);
                int co = (k >> 6)*6400 + ((k >> 3) & 7)*80 + (k & 7);
                uint32_t b_hi[4], b_lo[4];
                uint32_t bbyte = (uint32_t)(((((lane >> 4) << 3) + (lane & 7))*128) + (ks*16 + (lane & 8))*2);
                ldsm4(b_hi, bHiBase + sw128(bbyte));
                ldsm4(b_lo, bLoBase + sw128(bbyte));
#pragma unroll
                for (int mt = 0; mt < 2; mt++) {
                    const uint32_t* q0 = xp[mt*2 + 0];
                    const uint32_t* q1 = xp[mt*2 + 1];
                    bool v0 = pvh[mt*2 + 0], v1 = pvh[mt*2 + 1];
                    uint32_t w00 = v0 ? __ldg(q0 + co)      : 0u;
                    uint32_t w01 = v0 ? __ldg(q0 + co + 1)  : 0u;
                    uint32_t w02 = v0 ? __ldg(q0 + co + 80) : 0u;
                    uint32_t w03 = v0 ? __ldg(q0 + co + 81) : 0u;
                    uint32_t w10 = v1 ? __ldg(q1 + co)      : 0u;
                    uint32_t w11 = v1 ? __ldg(q1 + co + 1)  : 0u;
                    uint32_t w12 = v1 ? __ldg(q1 + co + 80) : 0u;
                    uint32_t w13 = v1 ? __ldg(q1 + co + 81) : 0u;
                    MMA_TERMS_N(2, acc + mt*8);
                }
            }
        }
    }
    __syncthreads();
    float* stg = (float*)smem;
#pragma unroll
    for (int h = 0; h < 2; h++) {
        if ((wid >> 2) == h) {
#pragma unroll
            for (int mt = 0; mt < 2; mt++)
#pragma unroll
                for (int nt = 0; nt < 2; nt++)
#pragma unroll
                    for (int r = 0; r < 4; r++) {
                        int row = (wid & 3)*32 + mt*16 + (lane >> 2) + ((r >> 1) << 3);
                        int col = nt*8 + ((lane & 3) << 1) + (r & 1);
                        stg[row*17 + col] = acc[(mt*2 + nt)*4 + r];
                    }
        }
        __syncthreads();
        {
            int r  = tid & 127;
            int j0 = (tid >> 7) * 8;
            int pq = blockIdx.x * 256 + h * 128 + r;
            if (pq < CONV4_M) {
                int xo2 = pq % 73, yo2 = (pq / 73) % 73, b2 = pq / 5329;
                float* op = g_c4 + (b2 * 16 * 73 + yo2) * 73 + xo2;
#pragma unroll
                for (int j = 0; j < 8; j++) {
                    int jj = j0 + j;
                    op[jj * 5329] = stg[r*17 + jj] + __ldg(bias + jj);
                }
            }
        }
        __syncthreads();
    }
}

// ------------------------- weight transpose for remaining direct convs -------------------------
#define DEFINE_TRANS(NAME, OC, R, DST)                                        \
__global__ void NAME(const float* __restrict__ w) {                           \
    int e = blockIdx.x * blockDim.x + threadIdx.x;                            \
    if (e < (OC)*(R)) {                                                       \
        int oc = e / (R);                                                     \
        int r  = e - oc * (R);                                                \
        DST[r*(OC) + oc] = w[e];                                              \
    }                                                                         \
}
DEFINE_TRANS(t_w5,  16, 1024, g_wT5)
DEFINE_TRANS(t_w6,  16,  576, g_wT6)
DEFINE_TRANS(t_w7,  16,  400, g_wT7)
DEFINE_TRANS(t_w8,  16,  144, g_wT8)
DEFINE_TRANS(t_wfc, 512, 1024, g_wTfc)

// ------------------------- generic OC=16 direct conv, 2 pixels/thread -------------------------
#define DEFINE_CONV16(NAME, IC, K, S, IH, IW, OH, OW, INBUF, WTBUF, OUTBUF)          \
__global__ void __launch_bounds__(128) NAME(const float* __restrict__ bias) {        \
    const int XP  = ((OW) + 1) / 2;                                                  \
    const int OFF = (OW) - XP;                                                       \
    int t = blockIdx.x * 128 + threadIdx.x;                                          \
    if (t >= BATCH * (OH) * XP) return;                                              \
    int xo = t % XP;                                                                 \
    int yo = (t / XP) % (OH);                                                        \
    int b  = t / (XP * (OH));                                                        \
    float a0[16], a1[16];                                                            \
    _Pragma("unroll")                                                                \
    for (int j = 0; j < 16; j++) { float bv = __ldg(bias + j); a0[j] = bv; a1[j] = bv; } \
    for (int ic = 0; ic < (IC); ic++) {                                              \
        const float* inp = INBUF + ((b*(IC) + ic)*(IH) + yo*(S))*(IW) + xo*(S);      \
        _Pragma("unroll 1")                                                          \
        for (int ky = 0; ky < (K); ky++) {                                           \
            const float* row = inp + ky*(IW);                                        \
            const float4* wrow = (const float4*)(WTBUF + (ic*(K)*(K) + ky*(K))*16);  \
            _Pragma("unroll")                                                        \
            for (int kx = 0; kx < (K); kx++) {                                       \
                float v0 = __ldg(row + kx);                                          \
                float v1 = __ldg(row + OFF*(S) + kx);                                \
                _Pragma("unroll")                                                    \
                for (int j = 0; j < 4; j++) {                                        \
                    float4 w4 = __ldg(wrow + kx*4 + j);                              \
                    a0[4*j+0] = fmaf(v0, w4.x, a0[4*j+0]); a1[4*j+0] = fmaf(v1, w4.x, a1[4*j+0]); \
                    a0[4*j+1] = fmaf(v0, w4.y, a0[4*j+1]); a1[4*j+1] = fmaf(v1, w4.y, a1[4*j+1]); \
                    a0[4*j+2] = fmaf(v0, w4.z, a0[4*j+2]); a1[4*j+2] = fmaf(v1, w4.z, a1[4*j+2]); \
                    a0[4*j+3] = fmaf(v0, w4.w, a0[4*j+3]); a1[4*j+3] = fmaf(v1, w4.w, a1[4*j+3]); \
                }                                                                    \
            }                                                                        \
        }                                                                            \
    }                                                                                \
    float* op = OUTBUF + (b*16*(OH) + yo)*(OW) + xo;                                 \
    _Pragma("unroll")                                                                \
    for (int j = 0; j < 16; j++) {                                                   \
        op[j*(OH)*(OW)]       = a0[j];                                               \
        op[j*(OH)*(OW) + OFF] = a1[j];                                               \
    }                                                                                \
}

DEFINE_CONV16(conv5_kernel, 16, 8, 2, 73, 73, 33, 33, g_c4, g_wT5, g_c5)
DEFINE_CONV16(conv6_kernel, 16, 6, 1, 33, 33, 28, 28, g_c5, g_wT6, g_c6)
DEFINE_CONV16(conv7_kernel, 16, 5, 1, 28, 28, 24, 24, g_c6, g_wT7, g_c7)
DEFINE_CONV16(conv8_kernel, 16, 3, 3, 24, 24,  8,  8, g_c7, g_wT8, g_c8)

// ------------------------- FC -------------------------
__global__ void fc_kernel(const float* __restrict__ bias, float* __restrict__ out) {
    __shared__ float sm[1024];
    int b = blockIdx.x;
    int o = threadIdx.x;
    sm[o]       = g_c8[b * 1024 + o];
    sm[o + 512] = g_c8[b * 1024 + o + 512];
    __syncthreads();
    float acc = __ldg(bias + o);
#pragma unroll 4
    for (int k = 0; k < 1024; k++)
        acc = fmaf(sm[k], g_wTfc[k * 512 + o], acc);
    out[b * 512 + o] = acc;
}

// ------------------------- launch -------------------------
static inline int gridFor(long n, int bs) { return (int)((n + bs - 1) / bs); }

extern "C" void kernel_launch(void* const* d_in, const int* in_sizes, int n_in,
                              void* d_out, int out_size) {
    const float* x        = (const float*)d_in[0];
    const float* conv1_w  = (const float*)d_in[1];
    const float* conv1_b  = (const float*)d_in[2];
    const float* bn_gamma = (const float*)d_in[3];
    const float* bn_beta  = (const float*)d_in[4];
    const float* prelu_a  = (const float*)d_in[5];
    const float* rconv_w  = (const float*)d_in[6];
    const float* rconv_b  = (const float*)d_in[7];
    const float* conv4_w  = (const float*)d_in[8];
    const float* conv4_b  = (const float*)d_in[9];
    const float* conv5_b  = (const float*)d_in[11];
    const float* conv6_b  = (const float*)d_in[13];
    const float* conv7_b  = (const float*)d_in[15];
    const float* conv8_b  = (const float*)d_in[17];
    const float* fc_b     = (const float*)d_in[19];
    float* out = (float*)d_out;

    cudaFuncSetAttribute(conv1_mma, cudaFuncAttributeMaxDynamicSharedMemorySize, C1_SM);
    cudaFuncSetAttribute(rconv_mma, cudaFuncAttributeMaxDynamicSharedMemorySize, RC_SM);
    cudaFuncSetAttribute(conv4_mma, cudaFuncAttributeMaxDynamicSharedMemorySize, C4_SM);

    // launches ordered so conv1_mma is the 4th launch (ncu captures launch #4)
    split_x<<<gridFor((long)BATCH*3*170*170, 256), 256>>>(x);
    t_w1hl<<<gridFor(32*384, 256), 256>>>(conv1_w);
    t_wrhl<<<gridFor(32*320, 256), 256>>>(rconv_w);
    conv1_mma<<<6400, 256, C1_SM>>>(conv1_b);

    t_w4hl<<<gridFor(16*2048, 256), 256>>>(conv4_w);
    t_w5 <<<gridFor(16*1024, 256), 256>>>((const float*)d_in[10]);
    t_w6 <<<gridFor(16*576,  256), 256>>>((const float*)d_in[12]);
    t_w7 <<<gridFor(16*400,  256), 256>>>((const float*)d_in[14]);
    t_w8 <<<gridFor(16*144,  256), 256>>>((const float*)d_in[16]);
    t_wfc<<<gridFor(512*1024,256), 256>>>((const float*)d_in[18]);

    stats_kernel<<<512, 256>>>(bn_gamma, bn_beta);
    act_kernel<<<gridFor((long)BATCH*32*160*160, 256), 256>>>(prelu_a);
    rconv_mma<<<6400, 256, RC_SM>>>(rconv_b);
    pool_kernel<<<gridFor((long)BATCH*32*80*80, 256), 256>>>();

    conv4_mma<<<gridFor(CONV4_M, 256), 256, C4_SM>>>(conv4_b);
    conv5_kernel<<<gridFor((long)BATCH*33*17, 128), 128>>>(conv5_b);
    conv6_kernel<<<gridFor((long)BATCH*28*14, 128), 128>>>(conv6_b);
    conv7_kernel<<<gridFor((long)BATCH*24*12, 128), 128>>>(conv7_b);
    conv8_kernel<<<gridFor((long)BATCH*8*4,   128), 128>>>(conv8_b);

    fc_kernel<<<BATCH, 512>>>(fc_b, out);
}